// round 3
// baseline (speedup 1.0000x reference)
#include <cuda_runtime.h>
#include <cuda_bf16.h>
#include <cstdint>

#define B_  128
#define LC  256
#define LE  1024
#define D_  256
#define M_  512
#define NEGV (-1e9f)

// ---------------- scratch (device globals; no allocs allowed) ----------------
__device__ float g_c    [(size_t)B_ * LC * D_];   // relu(criteria@Wa+ba), later reused as t1
__device__ float g_e    [(size_t)B_ * LE * D_];   // relu(ehr@Wa+ba), later reused as t2
__device__ float g_align[(size_t)B_ * LC * LE];   // align, overwritten in-place by beta
__device__ float g_alpha[(size_t)B_ * LC * LE];   // row softmax
__device__ float g_attc [(size_t)B_ * LC * D_];
__device__ float g_atte [(size_t)B_ * LE * D_];
__device__ float g_r1   [B_ * D_];
__device__ float g_r2   [B_ * D_];

// ---------------- generic tiled SGEMM ----------------
// C[M x N] = act( A * B + bias )
// MODE_A: 0 = A row-major (M x K), 1 = A stored K x M (transposed access),
//         2 = split A: cols [0,Ksplit) from A, [Ksplit,K) from A2 (both row-major, same lda)
// TRANSB: 0 = B row-major (K x N), 1 = B row-major (N x K) -> use B^T
// Tiles: BM=128, BN=64, BK=16; 256 threads; 8x4 micro-tile per thread.
// Assumes M%128==0, N%64==0, K%16==0 (true for every call here).
static const int BM = 128, BN = 64, BK = 16;

template <int MODE_A, int TRANSB, bool BIAS_RELU>
__global__ __launch_bounds__(256)
void gemm_kernel(const float* __restrict__ A, const float* __restrict__ A2,
                 const float* __restrict__ Bm, const float* __restrict__ bias,
                 float* __restrict__ C,
                 int M, int N, int K, int Ksplit,
                 int lda, int ldb, int ldc,
                 long long sA, long long sB, long long sC)
{
    const int bz = blockIdx.z;
    const float* Ab = A + (long long)bz * sA;
    const float* Bb = Bm + (long long)bz * sB;
    float* Cb = C + (long long)bz * sC;

    __shared__ float As[BK][BM];        // 8 KB
    __shared__ float Bs[BK][BN + 4];    // ~4.25 KB

    const int tid = threadIdx.x;
    const int tx = tid & 15;       // 16 cols of threads -> 4 cols each
    const int ty = tid >> 4;       // 16 rows of threads -> 8 rows each
    const int m0 = blockIdx.x * BM;
    const int n0 = blockIdx.y * BN;

    float acc[8][4] = {};

    for (int k0 = 0; k0 < K; k0 += BK) {
        // ---- load A tile into As[k][m]  (BM*BK = 2048 floats, 8 per thread) ----
        if (MODE_A == 1) {
            // A is (K x M): As[k][m] = A[(k0+k)*lda + m0+m]
            #pragma unroll
            for (int it = 0; it < 2; it++) {
                const int idx = tid + it * 256;       // 0..511 float4 slots
                const int k  = idx >> 5;              // 0..15
                const int mm = (idx & 31) * 4;        // 0..124
                const float4 v = *(const float4*)(Ab + (long long)(k0 + k) * lda + m0 + mm);
                As[k][mm + 0] = v.x; As[k][mm + 1] = v.y;
                As[k][mm + 2] = v.z; As[k][mm + 3] = v.w;
            }
        } else {
            const float* Asrc = Ab;
            int kk = k0;
            if (MODE_A == 2 && k0 >= Ksplit) { Asrc = A2 + (long long)0; kk = k0 - Ksplit; }
            const int r = tid >> 1;                   // 0..127
            const int c = (tid & 1) * 8;              // 0 or 8
            const float4 v0 = *(const float4*)(Asrc + (long long)(m0 + r) * lda + kk + c);
            const float4 v1 = *(const float4*)(Asrc + (long long)(m0 + r) * lda + kk + c + 4);
            As[c + 0][r] = v0.x; As[c + 1][r] = v0.y;
            As[c + 2][r] = v0.z; As[c + 3][r] = v0.w;
            As[c + 4][r] = v1.x; As[c + 5][r] = v1.y;
            As[c + 6][r] = v1.z; As[c + 7][r] = v1.w;
        }
        // ---- load B tile into Bs[k][n]  (BK*BN = 1024 floats, 4 per thread) ----
        if (TRANSB) {
            // B is (N x K): Bs[k][n] = B[(n0+n)*ldb + k0+k]
            const int n = tid >> 2;            // 0..63
            const int c = (tid & 3) * 4;       // 0,4,8,12
            const float4 v = *(const float4*)(Bb + (long long)(n0 + n) * ldb + k0 + c);
            Bs[c + 0][n] = v.x; Bs[c + 1][n] = v.y;
            Bs[c + 2][n] = v.z; Bs[c + 3][n] = v.w;
        } else {
            const int k  = tid >> 4;           // 0..15
            const int nn = (tid & 15) * 4;     // 0..60
            const float4 v = *(const float4*)(Bb + (long long)(k0 + k) * ldb + n0 + nn);
            *(float4*)&Bs[k][nn] = v;          // (BN+4)*4 = 272 B row pitch, 16B aligned
        }
        __syncthreads();

        #pragma unroll
        for (int k = 0; k < BK; k++) {
            const float4 av0 = *(const float4*)&As[k][ty * 8];
            const float4 av1 = *(const float4*)&As[k][ty * 8 + 4];
            const float4 bv  = *(const float4*)&Bs[k][tx * 4];
            const float a[8] = {av0.x, av0.y, av0.z, av0.w, av1.x, av1.y, av1.z, av1.w};
            const float b[4] = {bv.x, bv.y, bv.z, bv.w};
            #pragma unroll
            for (int i = 0; i < 8; i++)
                #pragma unroll
                for (int j = 0; j < 4; j++)
                    acc[i][j] += a[i] * b[j];
        }
        __syncthreads();
    }

    float4 bb = make_float4(0.f, 0.f, 0.f, 0.f);
    if (BIAS_RELU) bb = *(const float4*)&bias[n0 + tx * 4];

    #pragma unroll
    for (int i = 0; i < 8; i++) {
        float4 o;
        o.x = acc[i][0]; o.y = acc[i][1]; o.z = acc[i][2]; o.w = acc[i][3];
        if (BIAS_RELU) {
            o.x = fmaxf(o.x + bb.x, 0.f); o.y = fmaxf(o.y + bb.y, 0.f);
            o.z = fmaxf(o.z + bb.z, 0.f); o.w = fmaxf(o.w + bb.w, 0.f);
        }
        *(float4*)(Cb + (long long)(m0 + ty * 8 + i) * ldc + n0 + tx * 4) = o;
    }
}

// ---------------- masked softmax over Le (rows): alpha ----------------
__global__ __launch_bounds__(256)
void softmax_rows(const float* __restrict__ align, const int* __restrict__ emask,
                  float* __restrict__ out)
{
    const int row = blockIdx.x;          // b*LC + l
    const int b = row >> 8;              // /LC
    const float* a = align + (long long)row * LE;
    float* o = out + (long long)row * LE;
    const int* em = emask + b * LE;
    const int t = threadIdx.x;

    float vals[4];
    float mx = -3.4e38f;
    #pragma unroll
    for (int i = 0; i < 4; i++) {
        const int e = t + i * 256;
        float v = a[e] + (1.0f - (float)em[e]) * NEGV;
        vals[i] = v;
        mx = fmaxf(mx, v);
    }
    __shared__ float red[256];
    red[t] = mx; __syncthreads();
    for (int s = 128; s > 0; s >>= 1) {
        if (t < s) red[t] = fmaxf(red[t], red[t + s]);
        __syncthreads();
    }
    mx = red[0]; __syncthreads();

    float sum = 0.f;
    #pragma unroll
    for (int i = 0; i < 4; i++) { vals[i] = __expf(vals[i] - mx); sum += vals[i]; }
    red[t] = sum; __syncthreads();
    for (int s = 128; s > 0; s >>= 1) {
        if (t < s) red[t] += red[t + s];
        __syncthreads();
    }
    const float inv = 1.0f / red[0];
    #pragma unroll
    for (int i = 0; i < 4; i++) o[t + i * 256] = vals[i] * inv;
}

// ---------------- masked softmax over Lc (columns), in-place: beta ----------------
__global__ __launch_bounds__(256)
void softmax_cols_inplace(float* __restrict__ align, const int* __restrict__ cmask)
{
    const int b = blockIdx.y;
    const int e = blockIdx.x * 256 + threadIdx.x;
    float* a = align + (long long)b * LC * LE + e;
    const int* cm = cmask + b * LC;

    float mx = -3.4e38f;
    #pragma unroll 4
    for (int l = 0; l < LC; l++) {
        const float v = a[(long long)l * LE] + (1.0f - (float)cm[l]) * NEGV;
        mx = fmaxf(mx, v);
    }
    float sum = 0.f;
    #pragma unroll 4
    for (int l = 0; l < LC; l++) {
        const float v = a[(long long)l * LE] + (1.0f - (float)cm[l]) * NEGV;
        sum += __expf(v - mx);
    }
    const float inv = 1.0f / sum;
    #pragma unroll 4
    for (int l = 0; l < LC; l++) {
        const float v = a[(long long)l * LE] + (1.0f - (float)cm[l]) * NEGV;
        a[(long long)l * LE] = __expf(v - mx) * inv;
    }
}

// ---------------- column reduction: r[b,d] = sum_l t[b,l,d] ----------------
__global__ __launch_bounds__(256)
void reduce_r(const float* __restrict__ t, float* __restrict__ r, int L)
{
    const int b = blockIdx.x, d = threadIdx.x;
    const float* p = t + (long long)b * L * D_ + d;
    float s = 0.f;
    for (int l = 0; l < L; l++) s += p[(long long)l * D_];
    r[b * D_ + d] = s;
}

// ---------------- final MLP: one block per batch ----------------
__global__ __launch_bounds__(256)
void final_mlp(const float* __restrict__ r1, const float* __restrict__ r2,
               const float* __restrict__ Wm, const float* __restrict__ bm,
               const float* __restrict__ Wo, const float* __restrict__ bo,
               float* __restrict__ out)
{
    const int b = blockIdx.x;
    const int t = threadIdx.x;
    __shared__ float m[4 * D_];   // 1024
    __shared__ float h[M_];       // 512

    const float a = r1[b * D_ + t];
    const float c = r2[b * D_ + t];
    m[t] = a; m[D_ + t] = c; m[2 * D_ + t] = a * c; m[3 * D_ + t] = a - c;
    __syncthreads();

    for (int j = t; j < M_; j += 256) {
        float s = bm[j];
        #pragma unroll 8
        for (int k = 0; k < 4 * D_; k++) s += m[k] * Wm[k * M_ + j];
        h[j] = fmaxf(s, 0.f);
    }
    __syncthreads();

    float p0 = 0.f, p1 = 0.f, p2 = 0.f;
    for (int j = t; j < M_; j += 256) {
        const float hv = h[j];
        p0 += hv * Wo[j * 3 + 0];
        p1 += hv * Wo[j * 3 + 1];
        p2 += hv * Wo[j * 3 + 2];
    }
    __shared__ float red[3][256];
    red[0][t] = p0; red[1][t] = p1; red[2][t] = p2; __syncthreads();
    for (int s = 128; s > 0; s >>= 1) {
        if (t < s) {
            red[0][t] += red[0][t + s];
            red[1][t] += red[1][t + s];
            red[2][t] += red[2][t + s];
        }
        __syncthreads();
    }
    if (t < 3) out[b * 3 + t] = red[t][0] + bo[t];
}

// ---------------- host launcher ----------------
extern "C" void kernel_launch(void* const* d_in, const int* in_sizes, int n_in,
                              void* d_out, int out_size)
{
    const float *criteria = nullptr, *ehr = nullptr, *Wa = nullptr, *ba = nullptr,
                *Wr = nullptr, *br = nullptr, *Wm = nullptr, *bm = nullptr,
                *Wo = nullptr, *bo = nullptr;
    const int *cmask = nullptr, *emask = nullptr;

    // Resolve by element count; disambiguate the two 131072s (Wr vs ehr_mask) and
    // the two 256s (ba vs br) by neighbor sizes — robust under both dict order and
    // reference-signature order.
    for (int i = 0; i < n_in; i++) {
        const int s = in_sizes[i];
        switch (s) {
            case 8388608:  criteria = (const float*)d_in[i]; break;
            case 33554432: ehr      = (const float*)d_in[i]; break;
            case 32768:    cmask    = (const int*)d_in[i];   break;
            case 65536:    Wa       = (const float*)d_in[i]; break;
            case 524288:   Wm       = (const float*)d_in[i]; break;
            case 512:      bm       = (const float*)d_in[i]; break;
            case 1536:     Wo       = (const float*)d_in[i]; break;
            case 3:        bo       = (const float*)d_in[i]; break;
            case 131072: {
                const int prev = (i > 0) ? in_sizes[i - 1] : -1;
                if (prev == 256) Wr = (const float*)d_in[i];
                else             emask = (const int*)d_in[i];
                break;
            }
            case 256: {
                const int nxt = (i + 1 < n_in) ? in_sizes[i + 1] : -1;
                if (nxt == 131072) ba = (const float*)d_in[i];
                else               br = (const float*)d_in[i];
                break;
            }
            default: break;
        }
    }

    float *c_, *e_, *al_, *alp_, *atc_, *ate_, *r1_, *r2_;
    cudaGetSymbolAddress((void**)&c_,   g_c);
    cudaGetSymbolAddress((void**)&e_,   g_e);
    cudaGetSymbolAddress((void**)&al_,  g_align);
    cudaGetSymbolAddress((void**)&alp_, g_alpha);
    cudaGetSymbolAddress((void**)&atc_, g_attc);
    cudaGetSymbolAddress((void**)&ate_, g_atte);
    cudaGetSymbolAddress((void**)&r1_,  g_r1);
    cudaGetSymbolAddress((void**)&r2_,  g_r2);

    const dim3 blk(256);

    // 1) c = relu(criteria@Wa+ba): (B*LC=32768, 256) x (256,256)
    gemm_kernel<0, 0, true><<<dim3(256, 4, 1), blk>>>(
        criteria, nullptr, Wa, ba, c_, B_ * LC, D_, D_, 0, D_, D_, D_, 0, 0, 0);
    // 2) e = relu(ehr@Wa+ba): (131072, 256)
    gemm_kernel<0, 0, true><<<dim3(1024, 4, 1), blk>>>(
        ehr, nullptr, Wa, ba, e_, B_ * LE, D_, D_, 0, D_, D_, D_, 0, 0, 0);
    // 3) align[b] = c[b] @ e[b]^T  (256 x 1024, K=256), batched
    gemm_kernel<0, 1, false><<<dim3(2, 16, B_), blk>>>(
        c_, nullptr, e_, nullptr, al_, LC, LE, D_, 0, D_, D_, LE,
        (long long)LC * D_, (long long)LE * D_, (long long)LC * LE);
    // 4) alpha = softmax over Le (rows), masked by ehr_mask
    softmax_rows<<<B_ * LC, 256>>>(al_, emask, alp_);
    // 5) beta = softmax over Lc (columns), masked by criteria_mask, in-place
    softmax_cols_inplace<<<dim3(LE / 256, B_), 256>>>(al_, cmask);
    // 6) att_c[b] = alpha[b] @ ehr[b]  (256 x 256, K=1024)
    gemm_kernel<0, 0, false><<<dim3(2, 4, B_), blk>>>(
        alp_, nullptr, ehr, nullptr, atc_, LC, D_, LE, 0, LE, D_, D_,
        (long long)LC * LE, (long long)LE * D_, (long long)LC * D_);
    // 7) att_e[b] = beta[b]^T @ criteria[b]  (1024 x 256, K=256); A stored (Lc x Le)
    gemm_kernel<1, 0, false><<<dim3(8, 4, B_), blk>>>(
        al_, nullptr, criteria, nullptr, ate_, LE, D_, LC, 0, LE, D_, D_,
        (long long)LC * LE, (long long)LC * D_, (long long)LE * D_);
    // 8) t1 = relu([att_c|criteria] @ Wr + br): (32768, 256), K=512 split at 256 -> reuse g_c
    gemm_kernel<2, 0, true><<<dim3(256, 4, 1), blk>>>(
        atc_, criteria, Wr, br, c_, B_ * LC, D_, 2 * D_, D_, D_, D_, D_, 0, 0, 0);
    // 9) t2 = relu([att_e|ehr] @ Wr + br): (131072, 256) -> reuse g_e
    gemm_kernel<2, 0, true><<<dim3(1024, 4, 1), blk>>>(
        ate_, ehr, Wr, br, e_, B_ * LE, D_, 2 * D_, D_, D_, D_, D_, 0, 0, 0);
    // 10) r1 = sum over Lc, r2 = sum over Le
    reduce_r<<<B_, 256>>>(c_, r1_, LC);
    reduce_r<<<B_, 256>>>(e_, r2_, LE);
    // 11) final MLP -> (B, 3)
    final_mlp<<<B_, 256>>>(r1_, r2_, Wm, bm, Wo, bo, (float*)d_out);
}

// round 4
// speedup vs baseline: 1.6762x; 1.6762x over previous
#include <cuda_runtime.h>
#include <cuda_bf16.h>
#include <mma.h>
#include <cstdint>
#include <type_traits>

using namespace nvcuda;

#define B_  128
#define LC  256
#define LE  1024
#define D_  256
#define M_  512
#define NEGV (-1e9f)

// ---------------- scratch (device globals; no allocs allowed) ----------------
__device__ float g_c    [(size_t)B_ * LC * D_];   // relu(criteria@Wa+ba), later reused as t1
__device__ float g_e    [(size_t)B_ * LE * D_];   // relu(ehr@Wa+ba), later reused as t2
__device__ float g_align[(size_t)B_ * LC * LE];   // align, overwritten in-place by beta
__device__ float g_alpha[(size_t)B_ * LC * LE];   // row softmax
__device__ float g_attc [(size_t)B_ * LC * D_];
__device__ float g_atte [(size_t)B_ * LE * D_];
__device__ float g_r1   [B_ * D_];
__device__ float g_r2   [B_ * D_];

// ---------------- TF32 tensor-core GEMM ----------------
// C[M x N] = act( A * B + bias ), fp32 in/out, tf32 MMA with fp32 accumulate.
// MODE_A: 0 = A row-major (M x K)
//         1 = A stored (K x M) row-major  -> logical A = (stored)^T
//         2 = split A: k in [0,Ksplit) from A, [Ksplit,K) from A2 (row-major, same lda)
// TRANSB: 0 = B row-major (K x N), 1 = B stored (N x K) row-major -> logical B = (stored)^T
// Tiles: BM=BN=128, BK=32; 256 threads (8 warps); warp tile 32x64 (2x4 wmma 16x16x8).
// Requires M%128==0, N%128==0, K%32==0, Ksplit%32==0 (true for every call here).

template <int MODE_A, int TRANSB, bool BIAS_RELU>
__global__ __launch_bounds__(256)
void wgemm(const float* __restrict__ A, const float* __restrict__ A2,
           const float* __restrict__ Bm, const float* __restrict__ bias,
           float* __restrict__ C,
           int K, int Ksplit,
           int lda, int ldb, int ldc,
           long long sA, long long sB, long long sC)
{
    constexpr int BM = 128, BN = 128, BK = 32;
    constexpr int A_LD = (MODE_A == 1) ? (BM + 8) : (BK + 8);   // 136 : 40
    constexpr int ASZ  = (MODE_A == 1) ? BK * (BM + 8) : BM * (BK + 8);
    constexpr int B_LD = (TRANSB == 1) ? (BK + 8) : (BN + 8);   // 40 : 136
    constexpr int BSZ  = (TRANSB == 1) ? BN * (BK + 8) : BK * (BN + 8);
    constexpr int C_LD = BN + 4;                                 // 132
    constexpr int CSZ  = 64 * C_LD;                              // 8448 (half tile)
    constexpr int SMSZ = (ASZ + BSZ > CSZ) ? (ASZ + BSZ) : CSZ;

    __shared__ __align__(16) float sm[SMSZ];
    float* As = sm;
    float* Bs = sm + ASZ;

    const int bz = blockIdx.z;
    const float* Ab = A  + (long long)bz * sA;
    const float* Bb = Bm + (long long)bz * sB;
    float*       Cb = C  + (long long)bz * sC;

    const int tid  = threadIdx.x;
    const int warp = tid >> 5;
    const int wm   = warp >> 1;      // 0..3 -> row block of 32
    const int wn   = warp & 1;       // 0..1 -> col block of 64
    const int m0   = blockIdx.x * BM;
    const int n0   = blockIdx.y * BN;

    using ALayout = typename std::conditional<MODE_A == 1, wmma::col_major, wmma::row_major>::type;
    using BLayout = typename std::conditional<TRANSB == 1, wmma::col_major, wmma::row_major>::type;

    wmma::fragment<wmma::accumulator, 16, 16, 8, float> acc[2][4];
    #pragma unroll
    for (int i = 0; i < 2; i++)
        #pragma unroll
        for (int j = 0; j < 4; j++)
            wmma::fill_fragment(acc[i][j], 0.0f);

    for (int k0 = 0; k0 < K; k0 += BK) {
        // ---- stage A tile ----
        if (MODE_A == 1) {
            // stored K x M: As[k][m] (ld=136)
            const int k  = tid >> 3;             // 0..31
            const int mb = (tid & 7) * 16;       // 0..112
            #pragma unroll
            for (int c = 0; c < 4; c++) {
                const float4 v = *(const float4*)(Ab + (long long)(k0 + k) * lda + m0 + mb + c * 4);
                *(float4*)&As[k * A_LD + mb + c * 4] = v;
            }
        } else {
            const float* Asrc = Ab;
            int kk = k0;
            if (MODE_A == 2 && k0 >= Ksplit) { Asrc = A2; kk = k0 - Ksplit; }
            const int r  = tid >> 1;             // 0..127
            const int kb = (tid & 1) * 16;       // 0 or 16
            #pragma unroll
            for (int c = 0; c < 4; c++) {
                const float4 v = *(const float4*)(Asrc + (long long)(m0 + r) * lda + kk + kb + c * 4);
                *(float4*)&As[r * A_LD + kb + c * 4] = v;
            }
        }
        // ---- stage B tile ----
        if (TRANSB == 1) {
            // stored N x K: Bs[n][k] (ld=40), matrix_b col_major
            const int n  = tid >> 1;             // 0..127
            const int kb = (tid & 1) * 16;
            #pragma unroll
            for (int c = 0; c < 4; c++) {
                const float4 v = *(const float4*)(Bb + (long long)(n0 + n) * ldb + k0 + kb + c * 4);
                *(float4*)&Bs[n * B_LD + kb + c * 4] = v;
            }
        } else {
            // stored K x N: Bs[k][n] (ld=136)
            const int k  = tid >> 3;
            const int nb = (tid & 7) * 16;
            #pragma unroll
            for (int c = 0; c < 4; c++) {
                const float4 v = *(const float4*)(Bb + (long long)(k0 + k) * ldb + n0 + nb + c * 4);
                *(float4*)&Bs[k * B_LD + nb + c * 4] = v;
            }
        }
        __syncthreads();

        #pragma unroll
        for (int kk = 0; kk < BK; kk += 8) {
            wmma::fragment<wmma::matrix_a, 16, 16, 8, wmma::precision::tf32, ALayout> afr[2];
            wmma::fragment<wmma::matrix_b, 16, 16, 8, wmma::precision::tf32, BLayout> bfr[4];
            #pragma unroll
            for (int i = 0; i < 2; i++) {
                const int row = wm * 32 + i * 16;
                const float* p = (MODE_A == 1) ? &As[kk * A_LD + row]
                                               : &As[row * A_LD + kk];
                wmma::load_matrix_sync(afr[i], p, A_LD);
                #pragma unroll
                for (int t = 0; t < afr[i].num_elements; t++)
                    afr[i].x[t] = wmma::__float_to_tf32(afr[i].x[t]);
            }
            #pragma unroll
            for (int j = 0; j < 4; j++) {
                const int col = wn * 64 + j * 16;
                const float* p = (TRANSB == 1) ? &Bs[col * B_LD + kk]
                                               : &Bs[kk * B_LD + col];
                wmma::load_matrix_sync(bfr[j], p, B_LD);
                #pragma unroll
                for (int t = 0; t < bfr[j].num_elements; t++)
                    bfr[j].x[t] = wmma::__float_to_tf32(bfr[j].x[t]);
            }
            #pragma unroll
            for (int i = 0; i < 2; i++)
                #pragma unroll
                for (int j = 0; j < 4; j++)
                    wmma::mma_sync(acc[i][j], afr[i], bfr[j], acc[i][j]);
        }
        __syncthreads();
    }

    // ---- epilogue: two 64-row phases through reused smem ----
    float* Cs = sm;
    const int lane = tid & 31;
    float4 bb = make_float4(0.f, 0.f, 0.f, 0.f);
    if (BIAS_RELU) bb = *(const float4*)&bias[n0 + lane * 4];

    #pragma unroll
    for (int phase = 0; phase < 2; phase++) {
        if ((warp < 4) == (phase == 0)) {
            const int rbase = (wm & 1) * 32;
            #pragma unroll
            for (int i = 0; i < 2; i++)
                #pragma unroll
                for (int j = 0; j < 4; j++)
                    wmma::store_matrix_sync(&Cs[(rbase + i * 16) * C_LD + wn * 64 + j * 16],
                                            acc[i][j], C_LD, wmma::mem_row_major);
        }
        __syncthreads();
        #pragma unroll
        for (int it = 0; it < 8; it++) {
            const int r = it * 8 + warp;                 // 0..63
            float4 v = *(float4*)&Cs[r * C_LD + lane * 4];
            if (BIAS_RELU) {
                v.x = fmaxf(v.x + bb.x, 0.f); v.y = fmaxf(v.y + bb.y, 0.f);
                v.z = fmaxf(v.z + bb.z, 0.f); v.w = fmaxf(v.w + bb.w, 0.f);
            }
            *(float4*)(Cb + (long long)(m0 + phase * 64 + r) * ldc + n0 + lane * 4) = v;
        }
        __syncthreads();
    }
}

// ---------------- masked softmax over Le (rows): alpha ----------------
__global__ __launch_bounds__(256)
void softmax_rows(const float* __restrict__ align, const int* __restrict__ emask,
                  float* __restrict__ out)
{
    const int row = blockIdx.x;          // b*LC + l
    const int b = row >> 8;              // /LC
    const float* a = align + (long long)row * LE;
    float* o = out + (long long)row * LE;
    const int* em = emask + b * LE;
    const int t = threadIdx.x;

    float vals[4];
    float mx = -3.4e38f;
    #pragma unroll
    for (int i = 0; i < 4; i++) {
        const int e = t + i * 256;
        float v = a[e] + (1.0f - (float)em[e]) * NEGV;
        vals[i] = v;
        mx = fmaxf(mx, v);
    }
    __shared__ float red[256];
    red[t] = mx; __syncthreads();
    for (int s = 128; s > 0; s >>= 1) {
        if (t < s) red[t] = fmaxf(red[t], red[t + s]);
        __syncthreads();
    }
    mx = red[0]; __syncthreads();

    float sum = 0.f;
    #pragma unroll
    for (int i = 0; i < 4; i++) { vals[i] = __expf(vals[i] - mx); sum += vals[i]; }
    red[t] = sum; __syncthreads();
    for (int s = 128; s > 0; s >>= 1) {
        if (t < s) red[t] += red[t + s];
        __syncthreads();
    }
    const float inv = 1.0f / red[0];
    #pragma unroll
    for (int i = 0; i < 4; i++) o[t + i * 256] = vals[i] * inv;
}

// ---------------- masked softmax over Lc (columns), in-place: beta ----------------
__global__ __launch_bounds__(256)
void softmax_cols_inplace(float* __restrict__ align, const int* __restrict__ cmask)
{
    const int b = blockIdx.y;
    const int e = blockIdx.x * 256 + threadIdx.x;
    float* a = align + (long long)b * LC * LE + e;
    const int* cm = cmask + b * LC;

    float mx = -3.4e38f;
    #pragma unroll 4
    for (int l = 0; l < LC; l++) {
        const float v = a[(long long)l * LE] + (1.0f - (float)cm[l]) * NEGV;
        mx = fmaxf(mx, v);
    }
    float sum = 0.f;
    #pragma unroll 4
    for (int l = 0; l < LC; l++) {
        const float v = a[(long long)l * LE] + (1.0f - (float)cm[l]) * NEGV;
        sum += __expf(v - mx);
    }
    const float inv = 1.0f / sum;
    #pragma unroll 4
    for (int l = 0; l < LC; l++) {
        const float v = a[(long long)l * LE] + (1.0f - (float)cm[l]) * NEGV;
        a[(long long)l * LE] = __expf(v - mx) * inv;
    }
}

// ---------------- column reduction: r[b,d] = sum_l t[b,l,d] ----------------
__global__ __launch_bounds__(256)
void reduce_r(const float* __restrict__ t, float* __restrict__ r, int L)
{
    const int b = blockIdx.x, d = threadIdx.x;
    const float* p = t + (long long)b * L * D_ + d;
    float s = 0.f;
    for (int l = 0; l < L; l++) s += p[(long long)l * D_];
    r[b * D_ + d] = s;
}

// ---------------- final MLP: one block per batch ----------------
__global__ __launch_bounds__(256)
void final_mlp(const float* __restrict__ r1, const float* __restrict__ r2,
               const float* __restrict__ Wm, const float* __restrict__ bm,
               const float* __restrict__ Wo, const float* __restrict__ bo,
               float* __restrict__ out)
{
    const int b = blockIdx.x;
    const int t = threadIdx.x;
    __shared__ float m[4 * D_];   // 1024
    __shared__ float h[M_];       // 512

    const float a = r1[b * D_ + t];
    const float c = r2[b * D_ + t];
    m[t] = a; m[D_ + t] = c; m[2 * D_ + t] = a * c; m[3 * D_ + t] = a - c;
    __syncthreads();

    for (int j = t; j < M_; j += 256) {
        float s = bm[j];
        #pragma unroll 8
        for (int k = 0; k < 4 * D_; k++) s += m[k] * Wm[k * M_ + j];
        h[j] = fmaxf(s, 0.f);
    }
    __syncthreads();

    float p0 = 0.f, p1 = 0.f, p2 = 0.f;
    for (int j = t; j < M_; j += 256) {
        const float hv = h[j];
        p0 += hv * Wo[j * 3 + 0];
        p1 += hv * Wo[j * 3 + 1];
        p2 += hv * Wo[j * 3 + 2];
    }
    __shared__ float red[3][256];
    red[0][t] = p0; red[1][t] = p1; red[2][t] = p2; __syncthreads();
    for (int s = 128; s > 0; s >>= 1) {
        if (t < s) {
            red[0][t] += red[0][t + s];
            red[1][t] += red[1][t + s];
            red[2][t] += red[2][t + s];
        }
        __syncthreads();
    }
    if (t < 3) out[b * 3 + t] = red[t][0] + bo[t];
}

// ---------------- host launcher ----------------
extern "C" void kernel_launch(void* const* d_in, const int* in_sizes, int n_in,
                              void* d_out, int out_size)
{
    const float *criteria = nullptr, *ehr = nullptr, *Wa = nullptr, *ba = nullptr,
                *Wr = nullptr, *br = nullptr, *Wm = nullptr, *bm = nullptr,
                *Wo = nullptr, *bo = nullptr;
    const int *cmask = nullptr, *emask = nullptr;

    for (int i = 0; i < n_in; i++) {
        const int s = in_sizes[i];
        switch (s) {
            case 8388608:  criteria = (const float*)d_in[i]; break;
            case 33554432: ehr      = (const float*)d_in[i]; break;
            case 32768:    cmask    = (const int*)d_in[i];   break;
            case 65536:    Wa       = (const float*)d_in[i]; break;
            case 524288:   Wm       = (const float*)d_in[i]; break;
            case 512:      bm       = (const float*)d_in[i]; break;
            case 1536:     Wo       = (const float*)d_in[i]; break;
            case 3:        bo       = (const float*)d_in[i]; break;
            case 131072: {
                const int prev = (i > 0) ? in_sizes[i - 1] : -1;
                if (prev == 256) Wr = (const float*)d_in[i];
                else             emask = (const int*)d_in[i];
                break;
            }
            case 256: {
                const int nxt = (i + 1 < n_in) ? in_sizes[i + 1] : -1;
                if (nxt == 131072) ba = (const float*)d_in[i];
                else               br = (const float*)d_in[i];
                break;
            }
            default: break;
        }
    }

    float *c_, *e_, *al_, *alp_, *atc_, *ate_, *r1_, *r2_;
    cudaGetSymbolAddress((void**)&c_,   g_c);
    cudaGetSymbolAddress((void**)&e_,   g_e);
    cudaGetSymbolAddress((void**)&al_,  g_align);
    cudaGetSymbolAddress((void**)&alp_, g_alpha);
    cudaGetSymbolAddress((void**)&atc_, g_attc);
    cudaGetSymbolAddress((void**)&ate_, g_atte);
    cudaGetSymbolAddress((void**)&r1_,  g_r1);
    cudaGetSymbolAddress((void**)&r2_,  g_r2);

    const dim3 blk(256);

    // 1) c = relu(criteria@Wa+ba): (32768 x 256), K=256
    wgemm<0, 0, true><<<dim3(256, 2, 1), blk>>>(
        criteria, nullptr, Wa, ba, c_, D_, 0, D_, D_, D_, 0, 0, 0);
    // 2) e = relu(ehr@Wa+ba): (131072 x 256), K=256
    wgemm<0, 0, true><<<dim3(1024, 2, 1), blk>>>(
        ehr, nullptr, Wa, ba, e_, D_, 0, D_, D_, D_, 0, 0, 0);
    // 3) align[b] = c[b] @ e[b]^T: (256 x 1024), K=256, batched
    wgemm<0, 1, false><<<dim3(2, 8, B_), blk>>>(
        c_, nullptr, e_, nullptr, al_, D_, 0, D_, D_, LE,
        (long long)LC * D_, (long long)LE * D_, (long long)LC * LE);
    // 4) alpha = softmax over Le (rows), masked by ehr_mask
    softmax_rows<<<B_ * LC, 256>>>(al_, emask, alp_);
    // 5) beta = softmax over Lc (columns), masked by criteria_mask, in-place
    softmax_cols_inplace<<<dim3(LE / 256, B_), 256>>>(al_, cmask);
    // 6) att_c[b] = alpha[b] @ ehr[b]: (256 x 256), K=1024
    wgemm<0, 0, false><<<dim3(2, 2, B_), blk>>>(
        alp_, nullptr, ehr, nullptr, atc_, LE, 0, LE, D_, D_,
        (long long)LC * LE, (long long)LE * D_, (long long)LC * D_);
    // 7) att_e[b] = beta[b]^T @ criteria[b]: (1024 x 256), K=256; A stored (Lc x Le)
    wgemm<1, 0, false><<<dim3(8, 2, B_), blk>>>(
        al_, nullptr, criteria, nullptr, ate_, LC, 0, LE, D_, D_,
        (long long)LC * LE, (long long)LC * D_, (long long)LE * D_);
    // 8) t1 = relu([att_c|criteria] @ Wr + br): (32768 x 256), K=512 split at 256 -> reuse g_c
    wgemm<2, 0, true><<<dim3(256, 2, 1), blk>>>(
        atc_, criteria, Wr, br, c_, 2 * D_, D_, D_, D_, D_, 0, 0, 0);
    // 9) t2 = relu([att_e|ehr] @ Wr + br): (131072 x 256), K=512 -> reuse g_e
    wgemm<2, 0, true><<<dim3(1024, 2, 1), blk>>>(
        ate_, ehr, Wr, br, e_, 2 * D_, D_, D_, D_, D_, 0, 0, 0);
    // 10) r1 = sum over Lc, r2 = sum over Le
    reduce_r<<<B_, 256>>>(c_, r1_, LC);
    reduce_r<<<B_, 256>>>(e_, r2_, LE);
    // 11) final MLP -> (B, 3)
    final_mlp<<<B_, 256>>>(r1_, r2_, Wm, bm, Wo, bo, (float*)d_out);
}

// round 5
// speedup vs baseline: 1.7831x; 1.0638x over previous
#include <cuda_runtime.h>
#include <cuda_bf16.h>
#include <mma.h>
#include <cstdint>
#include <type_traits>

using namespace nvcuda;

#define B_  128
#define LC  256
#define LE  1024
#define D_  256
#define M_  512
#define NEGV (-1e9f)

// ---------------- scratch (device globals; no allocs allowed) ----------------
__device__ float g_c    [(size_t)B_ * LC * D_];
__device__ float g_e    [(size_t)B_ * LE * D_];
__device__ float g_align[(size_t)B_ * LC * LE];
__device__ float g_alpha[(size_t)B_ * LC * LE];
__device__ float g_attc [(size_t)B_ * LC * D_];
__device__ float g_atte [(size_t)B_ * LE * D_];
__device__ float g_r1   [B_ * D_];
__device__ float g_r2   [B_ * D_];

__device__ __forceinline__ void cp_async16(float* smem_dst, const float* gsrc) {
    const uint32_t s = (uint32_t)__cvta_generic_to_shared(smem_dst);
    asm volatile("cp.async.cg.shared.global [%0], [%1], 16;\n" :: "r"(s), "l"(gsrc));
}
__device__ __forceinline__ void cp_commit() { asm volatile("cp.async.commit_group;\n"); }
__device__ __forceinline__ void cp_wait0()  { asm volatile("cp.async.wait_group 0;\n"); }

// ---------------- TF32 tensor-core GEMM, 2-stage cp.async pipeline ----------------
// C[M x N] = act( A * B + bias ), fp32 in/out, tf32 MMA fp32 accumulate.
// MODE_A: 0 = A row-major (M x K); 1 = A stored (K x M) -> logical A^T;
//         2 = split A: k<Ksplit from A, else A2 (row-major, same lda)
// TRANSB: 0 = B row-major (K x N); 1 = B stored (N x K) -> logical B^T
// Tiles: BM=BN=128, BK=32; 256 threads (8 warps); warp tile 32x64.
// Requires M%128==0, N%128==0, K%32==0, Ksplit%32==0.

template <int MODE_A, int TRANSB, bool BIAS_RELU>
__global__ __launch_bounds__(256)
void wgemm(const float* __restrict__ A, const float* __restrict__ A2,
           const float* __restrict__ Bm, const float* __restrict__ bias,
           float* __restrict__ C,
           int K, int Ksplit,
           int lda, int ldb, int ldc,
           long long sA, long long sB, long long sC)
{
    constexpr int BM = 128, BN = 128, BK = 32;
    constexpr int A_LD = (MODE_A == 1) ? (BM + 8) : (BK + 8);   // 136 : 40
    constexpr int ASZ  = (MODE_A == 1) ? BK * (BM + 8) : BM * (BK + 8);
    constexpr int B_LD = (TRANSB == 1) ? (BK + 8) : (BN + 8);
    constexpr int BSZ  = (TRANSB == 1) ? BN * (BK + 8) : BK * (BN + 8);
    constexpr int STAGE = ASZ + BSZ;
    constexpr int C_LD = BN + 4;

    extern __shared__ __align__(16) float sm[];

    const int bz = blockIdx.z;
    const float* Ab = A  + (long long)bz * sA;
    const float* Bb = Bm + (long long)bz * sB;
    float*       Cb = C  + (long long)bz * sC;

    const int tid  = threadIdx.x;
    const int warp = tid >> 5;
    const int wm   = warp >> 1;
    const int wn   = warp & 1;
    const int m0   = blockIdx.x * BM;
    const int n0   = blockIdx.y * BN;

    using ALayout = typename std::conditional<MODE_A == 1, wmma::col_major, wmma::row_major>::type;
    using BLayout = typename std::conditional<TRANSB == 1, wmma::col_major, wmma::row_major>::type;

    wmma::fragment<wmma::accumulator, 16, 16, 8, float> acc[2][4];
    #pragma unroll
    for (int i = 0; i < 2; i++)
        #pragma unroll
        for (int j = 0; j < 4; j++)
            wmma::fill_fragment(acc[i][j], 0.0f);

    auto load_stage = [&](int s, int k0) {
        float* As = sm + s * STAGE;
        float* Bs = As + ASZ;
        // ---- A tile ----
        if (MODE_A == 1) {
            const int k  = tid >> 3;             // 0..31
            const int mb = (tid & 7) * 16;       // 0..112
            const float* src = Ab + (long long)(k0 + k) * lda + m0 + mb;
            float* dst = &As[k * A_LD + mb];
            #pragma unroll
            for (int c = 0; c < 4; c++) cp_async16(dst + c * 4, src + c * 4);
        } else {
            const float* Asrc = Ab;
            int kk = k0;
            if (MODE_A == 2 && k0 >= Ksplit) { Asrc = A2; kk = k0 - Ksplit; }
            const int r  = tid >> 1;             // 0..127
            const int kb = (tid & 1) * 16;
            const float* src = Asrc + (long long)(m0 + r) * lda + kk + kb;
            float* dst = &As[r * A_LD + kb];
            #pragma unroll
            for (int c = 0; c < 4; c++) cp_async16(dst + c * 4, src + c * 4);
        }
        // ---- B tile ----
        if (TRANSB == 1) {
            const int n  = tid >> 1;
            const int kb = (tid & 1) * 16;
            const float* src = Bb + (long long)(n0 + n) * ldb + k0 + kb;
            float* dst = &Bs[n * B_LD + kb];
            #pragma unroll
            for (int c = 0; c < 4; c++) cp_async16(dst + c * 4, src + c * 4);
        } else {
            const int k  = tid >> 3;
            const int nb = (tid & 7) * 16;
            const float* src = Bb + (long long)(k0 + k) * ldb + n0 + nb;
            float* dst = &Bs[k * B_LD + nb];
            #pragma unroll
            for (int c = 0; c < 4; c++) cp_async16(dst + c * 4, src + c * 4);
        }
    };

    const int nT = K / BK;
    load_stage(0, 0);
    cp_commit();

    for (int t = 0; t < nT; t++) {
        cp_wait0();
        __syncthreads();
        if (t + 1 < nT) { load_stage((t + 1) & 1, (t + 1) * BK); cp_commit(); }

        const float* As = sm + (t & 1) * STAGE;
        const float* Bs = As + ASZ;
        #pragma unroll
        for (int kk = 0; kk < BK; kk += 8) {
            wmma::fragment<wmma::matrix_a, 16, 16, 8, wmma::precision::tf32, ALayout> afr[2];
            wmma::fragment<wmma::matrix_b, 16, 16, 8, wmma::precision::tf32, BLayout> bfr[4];
            #pragma unroll
            for (int i = 0; i < 2; i++) {
                const int row = wm * 32 + i * 16;
                const float* p = (MODE_A == 1) ? &As[kk * A_LD + row]
                                               : &As[row * A_LD + kk];
                wmma::load_matrix_sync(afr[i], p, A_LD);
                #pragma unroll
                for (int x = 0; x < afr[i].num_elements; x++)
                    afr[i].x[x] = wmma::__float_to_tf32(afr[i].x[x]);
            }
            #pragma unroll
            for (int j = 0; j < 4; j++) {
                const int col = wn * 64 + j * 16;
                const float* p = (TRANSB == 1) ? &Bs[col * B_LD + kk]
                                               : &Bs[kk * B_LD + col];
                wmma::load_matrix_sync(bfr[j], p, B_LD);
                #pragma unroll
                for (int x = 0; x < bfr[j].num_elements; x++)
                    bfr[j].x[x] = wmma::__float_to_tf32(bfr[j].x[x]);
            }
            #pragma unroll
            for (int i = 0; i < 2; i++)
                #pragma unroll
                for (int j = 0; j < 4; j++)
                    wmma::mma_sync(acc[i][j], afr[i], bfr[j], acc[i][j]);
        }
        __syncthreads();
    }

    // ---- epilogue: two 64-row phases through reused smem ----
    float* Cs = sm;
    const int lane = tid & 31;
    float4 bb = make_float4(0.f, 0.f, 0.f, 0.f);
    if (BIAS_RELU) bb = *(const float4*)&bias[n0 + lane * 4];

    #pragma unroll
    for (int phase = 0; phase < 2; phase++) {
        if ((warp < 4) == (phase == 0)) {
            const int rbase = (wm & 1) * 32;
            #pragma unroll
            for (int i = 0; i < 2; i++)
                #pragma unroll
                for (int j = 0; j < 4; j++)
                    wmma::store_matrix_sync(&Cs[(rbase + i * 16) * C_LD + wn * 64 + j * 16],
                                            acc[i][j], C_LD, wmma::mem_row_major);
        }
        __syncthreads();
        #pragma unroll
        for (int it = 0; it < 8; it++) {
            const int r = it * 8 + warp;
            float4 v = *(float4*)&Cs[r * C_LD + lane * 4];
            if (BIAS_RELU) {
                v.x = fmaxf(v.x + bb.x, 0.f); v.y = fmaxf(v.y + bb.y, 0.f);
                v.z = fmaxf(v.z + bb.z, 0.f); v.w = fmaxf(v.w + bb.w, 0.f);
            }
            *(float4*)(Cb + (long long)(m0 + phase * 64 + r) * ldc + n0 + lane * 4) = v;
        }
        __syncthreads();
    }
}

// ---------------- masked softmax over Le (rows): alpha ----------------
__global__ __launch_bounds__(256)
void softmax_rows(const float* __restrict__ align, const int* __restrict__ emask,
                  float* __restrict__ out)
{
    const int row = blockIdx.x;
    const int b = row >> 8;
    const float* a = align + (long long)row * LE;
    float* o = out + (long long)row * LE;
    const int* em = emask + b * LE;
    const int t = threadIdx.x;

    float vals[4];
    float mx = -3.4e38f;
    #pragma unroll
    for (int i = 0; i < 4; i++) {
        const int e = t + i * 256;
        float v = a[e] + (1.0f - (float)em[e]) * NEGV;
        vals[i] = v;
        mx = fmaxf(mx, v);
    }
    __shared__ float red[256];
    red[t] = mx; __syncthreads();
    for (int s = 128; s > 0; s >>= 1) {
        if (t < s) red[t] = fmaxf(red[t], red[t + s]);
        __syncthreads();
    }
    mx = red[0]; __syncthreads();

    float sum = 0.f;
    #pragma unroll
    for (int i = 0; i < 4; i++) { vals[i] = __expf(vals[i] - mx); sum += vals[i]; }
    red[t] = sum; __syncthreads();
    for (int s = 128; s > 0; s >>= 1) {
        if (t < s) red[t] += red[t + s];
        __syncthreads();
    }
    const float inv = 1.0f / red[0];
    #pragma unroll
    for (int i = 0; i < 4; i++) o[t + i * 256] = vals[i] * inv;
}

// ---------------- masked softmax over Lc (columns), in-place: beta ----------------
__global__ __launch_bounds__(256)
void softmax_cols_inplace(float* __restrict__ align, const int* __restrict__ cmask)
{
    __shared__ float cmsk[LC];
    const int b = blockIdx.y;
    const int e = blockIdx.x * 256 + threadIdx.x;
    float* a = align + (long long)b * LC * LE + e;
    const int* cm = cmask + b * LC;
    cmsk[threadIdx.x] = (1.0f - (float)cm[threadIdx.x]) * NEGV;
    __syncthreads();

    // pass 1: max
    float mx = -3.4e38f;
    #pragma unroll 4
    for (int l = 0; l < LC; l++)
        mx = fmaxf(mx, a[(long long)l * LE] + cmsk[l]);
    // pass 2: sum of exp
    float sum = 0.f;
    #pragma unroll 4
    for (int l = 0; l < LC; l++)
        sum += __expf(a[(long long)l * LE] + cmsk[l] - mx);
    const float inv = 1.0f / sum;
    // pass 3: write (L2-resident by now)
    #pragma unroll 4
    for (int l = 0; l < LC; l++)
        a[(long long)l * LE] = __expf(a[(long long)l * LE] + cmsk[l] - mx) * inv;
}

// ---------------- column reduction: r[b,d] = sum_l t[b,l,d] ----------------
__global__ __launch_bounds__(256)
void reduce_r(const float* __restrict__ t, float* __restrict__ r, int L)
{
    const int b = blockIdx.x, d = threadIdx.x;
    const float* p = t + (long long)b * L * D_ + d;
    float s = 0.f;
    for (int l = 0; l < L; l++) s += p[(long long)l * D_];
    r[b * D_ + d] = s;
}

// ---------------- final MLP: one block per batch ----------------
__global__ __launch_bounds__(256)
void final_mlp(const float* __restrict__ r1, const float* __restrict__ r2,
               const float* __restrict__ Wm, const float* __restrict__ bm,
               const float* __restrict__ Wo, const float* __restrict__ bo,
               float* __restrict__ out)
{
    const int b = blockIdx.x;
    const int t = threadIdx.x;
    __shared__ float m[4 * D_];
    __shared__ float h[M_];

    const float a = r1[b * D_ + t];
    const float c = r2[b * D_ + t];
    m[t] = a; m[D_ + t] = c; m[2 * D_ + t] = a * c; m[3 * D_ + t] = a - c;
    __syncthreads();

    for (int j = t; j < M_; j += 256) {
        float s = bm[j];
        #pragma unroll 8
        for (int k = 0; k < 4 * D_; k++) s += m[k] * Wm[k * M_ + j];
        h[j] = fmaxf(s, 0.f);
    }
    __syncthreads();

    float p0 = 0.f, p1 = 0.f, p2 = 0.f;
    for (int j = t; j < M_; j += 256) {
        const float hv = h[j];
        p0 += hv * Wo[j * 3 + 0];
        p1 += hv * Wo[j * 3 + 1];
        p2 += hv * Wo[j * 3 + 2];
    }
    __shared__ float red[3][256];
    red[0][t] = p0; red[1][t] = p1; red[2][t] = p2; __syncthreads();
    for (int s = 128; s > 0; s >>= 1) {
        if (t < s) {
            red[0][t] += red[0][t + s];
            red[1][t] += red[1][t + s];
            red[2][t] += red[2][t + s];
        }
        __syncthreads();
    }
    if (t < 3) out[b * 3 + t] = red[t][0] + bo[t];
}

// ---------------- host launcher ----------------
static const int GSMEM = 2 * ((128 * 40) + (32 * 136)) * 4 > 81920
                       ? 2 * ((128 * 40) + (32 * 136)) * 4 : 81920;  // 81920 B worst case

extern "C" void kernel_launch(void* const* d_in, const int* in_sizes, int n_in,
                              void* d_out, int out_size)
{
    const float *criteria = nullptr, *ehr = nullptr, *Wa = nullptr, *ba = nullptr,
                *Wr = nullptr, *br = nullptr, *Wm = nullptr, *bm = nullptr,
                *Wo = nullptr, *bo = nullptr;
    const int *cmask = nullptr, *emask = nullptr;

    for (int i = 0; i < n_in; i++) {
        const int s = in_sizes[i];
        switch (s) {
            case 8388608:  criteria = (const float*)d_in[i]; break;
            case 33554432: ehr      = (const float*)d_in[i]; break;
            case 32768:    cmask    = (const int*)d_in[i];   break;
            case 65536:    Wa       = (const float*)d_in[i]; break;
            case 524288:   Wm       = (const float*)d_in[i]; break;
            case 512:      bm       = (const float*)d_in[i]; break;
            case 1536:     Wo       = (const float*)d_in[i]; break;
            case 3:        bo       = (const float*)d_in[i]; break;
            case 131072: {
                const int prev = (i > 0) ? in_sizes[i - 1] : -1;
                if (prev == 256) Wr = (const float*)d_in[i];
                else             emask = (const int*)d_in[i];
                break;
            }
            case 256: {
                const int nxt = (i + 1 < n_in) ? in_sizes[i + 1] : -1;
                if (nxt == 131072) ba = (const float*)d_in[i];
                else               br = (const float*)d_in[i];
                break;
            }
            default: break;
        }
    }

    static bool attr_done = false;
    if (!attr_done) {
        cudaFuncSetAttribute(wgemm<0,0,true>,  cudaFuncAttributeMaxDynamicSharedMemorySize, GSMEM);
        cudaFuncSetAttribute(wgemm<0,1,false>, cudaFuncAttributeMaxDynamicSharedMemorySize, GSMEM);
        cudaFuncSetAttribute(wgemm<0,0,false>, cudaFuncAttributeMaxDynamicSharedMemorySize, GSMEM);
        cudaFuncSetAttribute(wgemm<1,0,false>, cudaFuncAttributeMaxDynamicSharedMemorySize, GSMEM);
        cudaFuncSetAttribute(wgemm<2,0,true>,  cudaFuncAttributeMaxDynamicSharedMemorySize, GSMEM);
        attr_done = true;
    }

    float *c_, *e_, *al_, *alp_, *atc_, *ate_, *r1_, *r2_;
    cudaGetSymbolAddress((void**)&c_,   g_c);
    cudaGetSymbolAddress((void**)&e_,   g_e);
    cudaGetSymbolAddress((void**)&al_,  g_align);
    cudaGetSymbolAddress((void**)&alp_, g_alpha);
    cudaGetSymbolAddress((void**)&atc_, g_attc);
    cudaGetSymbolAddress((void**)&ate_, g_atte);
    cudaGetSymbolAddress((void**)&r1_,  g_r1);
    cudaGetSymbolAddress((void**)&r2_,  g_r2);

    const dim3 blk(256);

    // 1) c = relu(criteria@Wa+ba): (32768 x 256), K=256
    wgemm<0, 0, true><<<dim3(256, 2, 1), blk, GSMEM>>>(
        criteria, nullptr, Wa, ba, c_, D_, 0, D_, D_, D_, 0, 0, 0);
    // 2) e = relu(ehr@Wa+ba): (131072 x 256), K=256
    wgemm<0, 0, true><<<dim3(1024, 2, 1), blk, GSMEM>>>(
        ehr, nullptr, Wa, ba, e_, D_, 0, D_, D_, D_, 0, 0, 0);
    // 3) align[b] = c[b] @ e[b]^T: (256 x 1024), K=256, batched
    wgemm<0, 1, false><<<dim3(2, 8, B_), blk, GSMEM>>>(
        c_, nullptr, e_, nullptr, al_, D_, 0, D_, D_, LE,
        (long long)LC * D_, (long long)LE * D_, (long long)LC * LE);
    // 4) alpha = softmax over Le (rows)
    softmax_rows<<<B_ * LC, 256>>>(al_, emask, alp_);
    // 5) beta = softmax over Lc (columns), in-place
    softmax_cols_inplace<<<dim3(LE / 256, B_), 256>>>(al_, cmask);
    // 6) att_c[b] = alpha[b] @ ehr[b]: (256 x 256), K=1024
    wgemm<0, 0, false><<<dim3(2, 2, B_), blk, GSMEM>>>(
        alp_, nullptr, ehr, nullptr, atc_, LE, 0, LE, D_, D_,
        (long long)LC * LE, (long long)LE * D_, (long long)LC * D_);
    // 7) att_e[b] = beta[b]^T @ criteria[b]: (1024 x 256), K=256
    wgemm<1, 0, false><<<dim3(8, 2, B_), blk, GSMEM>>>(
        al_, nullptr, criteria, nullptr, ate_, LC, 0, LE, D_, D_,
        (long long)LC * LE, (long long)LC * D_, (long long)LE * D_);
    // 8) t1 = relu([att_c|criteria] @ Wr + br): (32768 x 256), K=512 split
    wgemm<2, 0, true><<<dim3(256, 2, 1), blk, GSMEM>>>(
        atc_, criteria, Wr, br, c_, 2 * D_, D_, D_, D_, D_, 0, 0, 0);
    // 9) t2 = relu([att_e|ehr] @ Wr + br): (131072 x 256), K=512 split
    wgemm<2, 0, true><<<dim3(1024, 2, 1), blk, GSMEM>>>(
        ate_, ehr, Wr, br, e_, 2 * D_, D_, D_, D_, D_, 0, 0, 0);
    // 10) reductions
    reduce_r<<<B_, 256>>>(c_, r1_, LC);
    reduce_r<<<B_, 256>>>(e_, r2_, LE);
    // 11) final MLP -> (B, 3)
    final_mlp<<<B_, 256>>>(r1_, r2_, Wm, bm, Wo, bo, (float*)d_out);
}

// round 6
// speedup vs baseline: 4.5063x; 2.5272x over previous
#include <cuda_runtime.h>
#include <cuda_bf16.h>
#include <mma.h>
#include <cstdint>
#include <type_traits>

using namespace nvcuda;

#define B_  128
#define LC  256
#define LE  1024
#define D_  256
#define M_  512
#define NEGV (-1e9f)

typedef __nv_bfloat16 bf16;

// ---------------- scratch (device globals; no allocs allowed) ----------------
// fp32
__device__ float g_align[(size_t)B_ * LC * LE];   // align (pre-softmax), fp32
__device__ float g_t1   [(size_t)B_ * LC * D_];   // relu([att_c|criteria]Wr+br)
__device__ float g_t2   [(size_t)B_ * LE * D_];
__device__ float g_r1   [B_ * D_];
__device__ float g_r2   [B_ * D_];
// bf16
__device__ bf16 g_crb  [(size_t)B_ * LC * D_];    // criteria bf16
__device__ bf16 g_ehb  [(size_t)B_ * LE * D_];    // ehr bf16
__device__ bf16 g_Wab  [D_ * D_];
__device__ bf16 g_Wrb  [2 * D_ * D_];
__device__ bf16 g_cb   [(size_t)B_ * LC * D_];    // relu(criteria@Wa+ba)
__device__ bf16 g_eb   [(size_t)B_ * LE * D_];    // relu(ehr@Wa+ba)
__device__ bf16 g_alb  [(size_t)B_ * LC * LE];    // alpha bf16
__device__ bf16 g_beb  [(size_t)B_ * LC * LE];    // beta bf16
__device__ bf16 g_atcb [(size_t)B_ * LC * D_];    // att_c bf16
__device__ bf16 g_ateb [(size_t)B_ * LE * D_];    // att_e bf16

__device__ __forceinline__ void cp_async16(void* smem_dst, const void* gsrc) {
    const uint32_t s = (uint32_t)__cvta_generic_to_shared(smem_dst);
    asm volatile("cp.async.cg.shared.global [%0], [%1], 16;\n" :: "r"(s), "l"(gsrc));
}
__device__ __forceinline__ void cp_commit() { asm volatile("cp.async.commit_group;\n"); }
__device__ __forceinline__ void cp_wait0()  { asm volatile("cp.async.wait_group 0;\n"); }

// ---------------- fp32 -> bf16 convert ----------------
__global__ __launch_bounds__(256)
void convert_f2b(const float* __restrict__ src, bf16* __restrict__ dst, int n4)
{
    const int i = blockIdx.x * 256 + threadIdx.x;
    if (i < n4) {
        const float4 v = ((const float4*)src)[i];
        __nv_bfloat162 lo = __floats2bfloat162_rn(v.x, v.y);
        __nv_bfloat162 hi = __floats2bfloat162_rn(v.z, v.w);
        uint2 o;
        o.x = *(uint32_t*)&lo; o.y = *(uint32_t*)&hi;
        ((uint2*)dst)[i] = o;
    }
}

// ---------------- bf16 tensor-core GEMM, 2-stage cp.async pipeline ----------------
// C[M x N] = act( A * B + bias ); A,B bf16, fp32 accumulate; C fp32 or bf16.
// MODE_A: 0 = A row-major (M x K); 1 = A stored (K x M) -> logical A^T;
//         2 = split A: k<Ksplit from A, else A2 (row-major, same lda)
// TRANSB: 0 = B row-major (K x N); 1 = B stored (N x K) -> logical B^T
// Tiles: BM=BN=128, BK=32; 256 threads (8 warps); warp tile 32x64 (2x4 frags 16x16x16).
// Requires M%128==0, N%128==0, K%32==0, Ksplit%32==0.

template <int MODE_A, int TRANSB, bool OUT_BF16, bool BIAS_RELU>
__global__ __launch_bounds__(256)
void bgemm(const bf16* __restrict__ A, const bf16* __restrict__ A2,
           const bf16* __restrict__ Bm, const float* __restrict__ bias,
           void* __restrict__ C,
           int K, int Ksplit,
           int lda, int ldb, int ldc,
           long long sA, long long sB, long long sC)
{
    constexpr int BM = 128, BN = 128, BK = 32;
    constexpr int A_LD = (MODE_A == 1) ? (BM + 8) : (BK + 8);   // 136 : 40 (bf16)
    constexpr int ASZ  = (MODE_A == 1) ? BK * (BM + 8) : BM * (BK + 8);
    constexpr int B_LD = (TRANSB == 1) ? (BK + 8) : (BN + 8);
    constexpr int BSZ  = (TRANSB == 1) ? BN * (BK + 8) : BK * (BN + 8);
    constexpr int STAGE = ASZ + BSZ;       // bf16 elements
    constexpr int C_LD = BN + 4;           // fp32 epilogue staging

    extern __shared__ __align__(16) char smraw[];
    bf16* smb = (bf16*)smraw;

    const int bz = blockIdx.z;
    const bf16* Ab = A  + (long long)bz * sA;
    const bf16* Bb = Bm + (long long)bz * sB;

    const int tid  = threadIdx.x;
    const int warp = tid >> 5;
    const int wm   = warp >> 1;
    const int wn   = warp & 1;
    const int m0   = blockIdx.x * BM;
    const int n0   = blockIdx.y * BN;

    using ALayout = typename std::conditional<MODE_A == 1, wmma::col_major, wmma::row_major>::type;
    using BLayout = typename std::conditional<TRANSB == 1, wmma::col_major, wmma::row_major>::type;

    wmma::fragment<wmma::accumulator, 16, 16, 16, float> acc[2][4];
    #pragma unroll
    for (int i = 0; i < 2; i++)
        #pragma unroll
        for (int j = 0; j < 4; j++)
            wmma::fill_fragment(acc[i][j], 0.0f);

    auto load_stage = [&](int s, int k0) {
        bf16* As = smb + s * STAGE;
        bf16* Bs = As + ASZ;
        // ---- A tile: 128x32 (or 32x128) bf16 = 512 16B-chunks, 2 per thread ----
        #pragma unroll
        for (int it = 0; it < 2; it++) {
            const int cch = tid + it * 256;       // 0..511
            if (MODE_A == 1) {
                const int k  = cch >> 4;          // 0..31
                const int mb = (cch & 15) * 8;    // 0..120
                cp_async16(&As[k * A_LD + mb], Ab + (long long)(k0 + k) * lda + m0 + mb);
            } else {
                const bf16* Asrc = Ab;
                int kk = k0;
                if (MODE_A == 2 && k0 >= Ksplit) { Asrc = A2; kk = k0 - Ksplit; }
                const int r  = cch >> 2;          // 0..127
                const int kb = (cch & 3) * 8;     // 0..24
                cp_async16(&As[r * A_LD + kb], Asrc + (long long)(m0 + r) * lda + kk + kb);
            }
        }
        // ---- B tile ----
        #pragma unroll
        for (int it = 0; it < 2; it++) {
            const int cch = tid + it * 256;
            if (TRANSB == 1) {
                const int n  = cch >> 2;
                const int kb = (cch & 3) * 8;
                cp_async16(&Bs[n * B_LD + kb], Bb + (long long)(n0 + n) * ldb + k0 + kb);
            } else {
                const int k  = cch >> 4;
                const int nb = (cch & 15) * 8;
                cp_async16(&Bs[k * B_LD + nb], Bb + (long long)(k0 + k) * ldb + n0 + nb);
            }
        }
    };

    const int nT = K / BK;
    load_stage(0, 0);
    cp_commit();

    for (int t = 0; t < nT; t++) {
        cp_wait0();
        __syncthreads();
        if (t + 1 < nT) { load_stage((t + 1) & 1, (t + 1) * BK); cp_commit(); }

        const bf16* As = smb + (t & 1) * STAGE;
        const bf16* Bs = As + ASZ;
        #pragma unroll
        for (int kk = 0; kk < BK; kk += 16) {
            wmma::fragment<wmma::matrix_a, 16, 16, 16, bf16, ALayout> afr[2];
            wmma::fragment<wmma::matrix_b, 16, 16, 16, bf16, BLayout> bfr[4];
            #pragma unroll
            for (int i = 0; i < 2; i++) {
                const int row = wm * 32 + i * 16;
                const bf16* p = (MODE_A == 1) ? &As[kk * A_LD + row]
                                              : &As[row * A_LD + kk];
                wmma::load_matrix_sync(afr[i], p, A_LD);
            }
            #pragma unroll
            for (int j = 0; j < 4; j++) {
                const int col = wn * 64 + j * 16;
                const bf16* p = (TRANSB == 1) ? &Bs[col * B_LD + kk]
                                              : &Bs[kk * B_LD + col];
                wmma::load_matrix_sync(bfr[j], p, B_LD);
            }
            #pragma unroll
            for (int i = 0; i < 2; i++)
                #pragma unroll
                for (int j = 0; j < 4; j++)
                    wmma::mma_sync(acc[i][j], afr[i], bfr[j], acc[i][j]);
        }
        __syncthreads();
    }

    // ---- epilogue: two 64-row phases through reused smem (fp32 staging) ----
    float* Cs = (float*)smraw;
    const int lane = tid & 31;
    float4 bb = make_float4(0.f, 0.f, 0.f, 0.f);
    if (BIAS_RELU) bb = *(const float4*)&bias[n0 + lane * 4];

    #pragma unroll
    for (int phase = 0; phase < 2; phase++) {
        if ((warp < 4) == (phase == 0)) {
            const int rbase = (wm & 1) * 32;
            #pragma unroll
            for (int i = 0; i < 2; i++)
                #pragma unroll
                for (int j = 0; j < 4; j++)
                    wmma::store_matrix_sync(&Cs[(rbase + i * 16) * C_LD + wn * 64 + j * 16],
                                            acc[i][j], C_LD, wmma::mem_row_major);
        }
        __syncthreads();
        #pragma unroll
        for (int it = 0; it < 8; it++) {
            const int r = it * 8 + warp;
            float4 v = *(float4*)&Cs[r * C_LD + lane * 4];
            if (BIAS_RELU) {
                v.x = fmaxf(v.x + bb.x, 0.f); v.y = fmaxf(v.y + bb.y, 0.f);
                v.z = fmaxf(v.z + bb.z, 0.f); v.w = fmaxf(v.w + bb.w, 0.f);
            }
            const long long row = (long long)(m0 + phase * 64 + r);
            if (OUT_BF16) {
                bf16* Cb = (bf16*)C + (long long)bz * sC;
                __nv_bfloat162 lo = __floats2bfloat162_rn(v.x, v.y);
                __nv_bfloat162 hi = __floats2bfloat162_rn(v.z, v.w);
                uint2 o; o.x = *(uint32_t*)&lo; o.y = *(uint32_t*)&hi;
                *(uint2*)(Cb + row * ldc + n0 + lane * 4) = o;
            } else {
                float* Cb = (float*)C + (long long)bz * sC;
                *(float4*)(Cb + row * ldc + n0 + lane * 4) = v;
            }
        }
        __syncthreads();
    }
}

// ---------------- masked softmax over Le (rows) -> bf16 alpha ----------------
__global__ __launch_bounds__(256)
void softmax_rows(const float* __restrict__ align, const int* __restrict__ emask,
                  bf16* __restrict__ out)
{
    const int row = blockIdx.x;
    const int b = row >> 8;
    const float* a = align + (long long)row * LE;
    bf16* o = out + (long long)row * LE;
    const int* em = emask + b * LE;
    const int t = threadIdx.x;

    float vals[4];
    float mx = -3.4e38f;
    #pragma unroll
    for (int i = 0; i < 4; i++) {
        const int e = t + i * 256;
        float v = a[e] + (1.0f - (float)em[e]) * NEGV;
        vals[i] = v;
        mx = fmaxf(mx, v);
    }
    __shared__ float red[256];
    red[t] = mx; __syncthreads();
    for (int s = 128; s > 0; s >>= 1) {
        if (t < s) red[t] = fmaxf(red[t], red[t + s]);
        __syncthreads();
    }
    mx = red[0]; __syncthreads();

    float sum = 0.f;
    #pragma unroll
    for (int i = 0; i < 4; i++) { vals[i] = __expf(vals[i] - mx); sum += vals[i]; }
    red[t] = sum; __syncthreads();
    for (int s = 128; s > 0; s >>= 1) {
        if (t < s) red[t] += red[t + s];
        __syncthreads();
    }
    const float inv = 1.0f / red[0];
    #pragma unroll
    for (int i = 0; i < 4; i++) o[t + i * 256] = __float2bfloat16(vals[i] * inv);
}

// ---------------- masked softmax over Lc (columns) -> bf16 beta ----------------
__global__ __launch_bounds__(256)
void softmax_cols(const float* __restrict__ align, const int* __restrict__ cmask,
                  bf16* __restrict__ out)
{
    __shared__ float cmsk[LC];
    const int b = blockIdx.y;
    const int e = blockIdx.x * 256 + threadIdx.x;
    const float* a = align + (long long)b * LC * LE + e;
    bf16* o = out + (long long)b * LC * LE + e;
    const int* cm = cmask + b * LC;
    cmsk[threadIdx.x] = (1.0f - (float)cm[threadIdx.x]) * NEGV;
    __syncthreads();

    float mx = -3.4e38f;
    #pragma unroll 4
    for (int l = 0; l < LC; l++)
        mx = fmaxf(mx, a[(long long)l * LE] + cmsk[l]);
    float sum = 0.f;
    #pragma unroll 4
    for (int l = 0; l < LC; l++)
        sum += __expf(a[(long long)l * LE] + cmsk[l] - mx);
    const float inv = 1.0f / sum;
    #pragma unroll 4
    for (int l = 0; l < LC; l++)
        o[(long long)l * LE] = __float2bfloat16(__expf(a[(long long)l * LE] + cmsk[l] - mx) * inv);
}

// ---------------- column reduction: r[b,d] = sum_l t[b,l,d] ----------------
__global__ __launch_bounds__(256)
void reduce_r(const float* __restrict__ t, float* __restrict__ r, int L)
{
    const int b = blockIdx.x, d = threadIdx.x;
    const float* p = t + (long long)b * L * D_ + d;
    float s = 0.f;
    for (int l = 0; l < L; l++) s += p[(long long)l * D_];
    r[b * D_ + d] = s;
}

// ---------------- final MLP: one block per batch ----------------
__global__ __launch_bounds__(256)
void final_mlp(const float* __restrict__ r1, const float* __restrict__ r2,
               const float* __restrict__ Wm, const float* __restrict__ bm,
               const float* __restrict__ Wo, const float* __restrict__ bo,
               float* __restrict__ out)
{
    const int b = blockIdx.x;
    const int t = threadIdx.x;
    __shared__ float m[4 * D_];
    __shared__ float h[M_];

    const float a = r1[b * D_ + t];
    const float c = r2[b * D_ + t];
    m[t] = a; m[D_ + t] = c; m[2 * D_ + t] = a * c; m[3 * D_ + t] = a - c;
    __syncthreads();

    for (int j = t; j < M_; j += 256) {
        float s = bm[j];
        #pragma unroll 8
        for (int k = 0; k < 4 * D_; k++) s += m[k] * Wm[k * M_ + j];
        h[j] = fmaxf(s, 0.f);
    }
    __syncthreads();

    float p0 = 0.f, p1 = 0.f, p2 = 0.f;
    for (int j = t; j < M_; j += 256) {
        const float hv = h[j];
        p0 += hv * Wo[j * 3 + 0];
        p1 += hv * Wo[j * 3 + 1];
        p2 += hv * Wo[j * 3 + 2];
    }
    __shared__ float red[3][256];
    red[0][t] = p0; red[1][t] = p1; red[2][t] = p2; __syncthreads();
    for (int s = 128; s > 0; s >>= 1) {
        if (t < s) {
            red[0][t] += red[0][t + s];
            red[1][t] += red[1][t + s];
            red[2][t] += red[2][t + s];
        }
        __syncthreads();
    }
    if (t < 3) out[b * 3 + t] = red[t][0] + bo[t];
}

// ---------------- host launcher ----------------
static const int GSMEM = 44 * 1024;   // covers worst stage pair + fp32 epilogue staging

extern "C" void kernel_launch(void* const* d_in, const int* in_sizes, int n_in,
                              void* d_out, int out_size)
{
    const float *criteria = nullptr, *ehr = nullptr, *Wa = nullptr, *ba = nullptr,
                *Wr = nullptr, *br = nullptr, *Wm = nullptr, *bm = nullptr,
                *Wo = nullptr, *bo = nullptr;
    const int *cmask = nullptr, *emask = nullptr;

    for (int i = 0; i < n_in; i++) {
        const int s = in_sizes[i];
        switch (s) {
            case 8388608:  criteria = (const float*)d_in[i]; break;
            case 33554432: ehr      = (const float*)d_in[i]; break;
            case 32768:    cmask    = (const int*)d_in[i];   break;
            case 65536:    Wa       = (const float*)d_in[i]; break;
            case 524288:   Wm       = (const float*)d_in[i]; break;
            case 512:      bm       = (const float*)d_in[i]; break;
            case 1536:     Wo       = (const float*)d_in[i]; break;
            case 3:        bo       = (const float*)d_in[i]; break;
            case 131072: {
                const int prev = (i > 0) ? in_sizes[i - 1] : -1;
                if (prev == 256) Wr = (const float*)d_in[i];
                else             emask = (const int*)d_in[i];
                break;
            }
            case 256: {
                const int nxt = (i + 1 < n_in) ? in_sizes[i + 1] : -1;
                if (nxt == 131072) ba = (const float*)d_in[i];
                else               br = (const float*)d_in[i];
                break;
            }
            default: break;
        }
    }

    float *al_, *t1_, *t2_, *r1_, *r2_;
    bf16 *crb, *ehb, *Wab, *Wrb, *cb, *eb, *alb, *beb, *atcb, *ateb;
    cudaGetSymbolAddress((void**)&al_,  g_align);
    cudaGetSymbolAddress((void**)&t1_,  g_t1);
    cudaGetSymbolAddress((void**)&t2_,  g_t2);
    cudaGetSymbolAddress((void**)&r1_,  g_r1);
    cudaGetSymbolAddress((void**)&r2_,  g_r2);
    cudaGetSymbolAddress((void**)&crb,  g_crb);
    cudaGetSymbolAddress((void**)&ehb,  g_ehb);
    cudaGetSymbolAddress((void**)&Wab,  g_Wab);
    cudaGetSymbolAddress((void**)&Wrb,  g_Wrb);
    cudaGetSymbolAddress((void**)&cb,   g_cb);
    cudaGetSymbolAddress((void**)&eb,   g_eb);
    cudaGetSymbolAddress((void**)&alb,  g_alb);
    cudaGetSymbolAddress((void**)&beb,  g_beb);
    cudaGetSymbolAddress((void**)&atcb, g_atcb);
    cudaGetSymbolAddress((void**)&ateb, g_ateb);

    const dim3 blk(256);

    // 0) fp32 -> bf16 conversions
    convert_f2b<<<(B_*LC*D_/4 + 255)/256, 256>>>(criteria, crb, B_*LC*D_/4);
    convert_f2b<<<(B_*LE*D_/4 + 255)/256, 256>>>(ehr,      ehb, B_*LE*D_/4);
    convert_f2b<<<(D_*D_/4   + 255)/256, 256>>>(Wa,       Wab, D_*D_/4);
    convert_f2b<<<(2*D_*D_/4 + 255)/256, 256>>>(Wr,       Wrb, 2*D_*D_/4);

    // 1) c = relu(criteria@Wa+ba): (32768 x 256), K=256 -> bf16
    bgemm<0, 0, true, true><<<dim3(256, 2, 1), blk, GSMEM>>>(
        crb, nullptr, Wab, ba, cb, D_, 0, D_, D_, D_, 0, 0, 0);
    // 2) e = relu(ehr@Wa+ba): (131072 x 256), K=256 -> bf16
    bgemm<0, 0, true, true><<<dim3(1024, 2, 1), blk, GSMEM>>>(
        ehb, nullptr, Wab, ba, eb, D_, 0, D_, D_, D_, 0, 0, 0);
    // 3) align[b] = c[b] @ e[b]^T: (256 x 1024), K=256, batched -> fp32
    bgemm<0, 1, false, false><<<dim3(2, 8, B_), blk, GSMEM>>>(
        cb, nullptr, eb, nullptr, al_, D_, 0, D_, D_, LE,
        (long long)LC * D_, (long long)LE * D_, (long long)LC * LE);
    // 4) alpha = softmax over Le (rows) -> bf16
    softmax_rows<<<B_ * LC, 256>>>(al_, emask, alb);
    // 5) beta = softmax over Lc (columns) -> bf16
    softmax_cols<<<dim3(LE / 256, B_), 256>>>(al_, cmask, beb);
    // 6) att_c[b] = alpha[b] @ ehr[b]: (256 x 256), K=1024 -> bf16
    bgemm<0, 0, true, false><<<dim3(2, 2, B_), blk, GSMEM>>>(
        alb, nullptr, ehb, nullptr, atcb, LE, 0, LE, D_, D_,
        (long long)LC * LE, (long long)LE * D_, (long long)LC * D_);
    // 7) att_e[b] = beta[b]^T @ criteria[b]: (1024 x 256), K=256 -> bf16
    bgemm<1, 0, true, false><<<dim3(8, 2, B_), blk, GSMEM>>>(
        beb, nullptr, crb, nullptr, ateb, LC, 0, LE, D_, D_,
        (long long)LC * LE, (long long)LC * D_, (long long)LE * D_);
    // 8) t1 = relu([att_c|criteria] @ Wr + br): (32768 x 256), K=512 split -> fp32
    bgemm<2, 0, false, true><<<dim3(256, 2, 1), blk, GSMEM>>>(
        atcb, crb, Wrb, br, t1_, 2 * D_, D_, D_, D_, D_, 0, 0, 0);
    // 9) t2 = relu([att_e|ehr] @ Wr + br): (131072 x 256), K=512 split -> fp32
    bgemm<2, 0, false, true><<<dim3(1024, 2, 1), blk, GSMEM>>>(
        ateb, ehb, Wrb, br, t2_, 2 * D_, D_, D_, D_, D_, 0, 0, 0);
    // 10) reductions
    reduce_r<<<B_, 256>>>(t1_, r1_, LC);
    reduce_r<<<B_, 256>>>(t2_, r2_, LE);
    // 11) final MLP -> (B, 3)
    final_mlp<<<B_, 256>>>(r1_, r2_, Wm, bm, Wo, bo, (float*)d_out);
}

// round 9
// speedup vs baseline: 5.0225x; 1.1145x over previous
#include <cuda_runtime.h>
#include <cuda_bf16.h>
#include <mma.h>
#include <cstdint>
#include <type_traits>

using namespace nvcuda;

#define B_  128
#define LC  256
#define LE  1024
#define D_  256
#define M_  512
#define NEGV (-1e9f)

typedef __nv_bfloat16 bf16;

// ---------------- scratch (device globals; no allocs allowed) ----------------
__device__ float g_align[(size_t)B_ * LC * LE];   // align (pre-softmax), fp32
__device__ float g_r1   [B_ * D_];
__device__ float g_r2   [B_ * D_];
__device__ bf16 g_crb  [(size_t)B_ * LC * D_];    // criteria bf16
__device__ bf16 g_ehb  [(size_t)B_ * LE * D_];    // ehr bf16
__device__ bf16 g_Wab  [D_ * D_];
__device__ bf16 g_Wrb  [2 * D_ * D_];
__device__ bf16 g_cb   [(size_t)B_ * LC * D_];    // relu(criteria@Wa+ba)
__device__ bf16 g_eb   [(size_t)B_ * LE * D_];    // relu(ehr@Wa+ba)
__device__ bf16 g_alb  [(size_t)B_ * LC * LE];    // alpha bf16
__device__ bf16 g_beb  [(size_t)B_ * LC * LE];    // beta bf16
__device__ bf16 g_atcb [(size_t)B_ * LC * D_];    // att_c bf16
__device__ bf16 g_ateb [(size_t)B_ * LE * D_];    // att_e bf16

__device__ __forceinline__ void cp_async16(void* smem_dst, const void* gsrc) {
    const uint32_t s = (uint32_t)__cvta_generic_to_shared(smem_dst);
    asm volatile("cp.async.cg.shared.global [%0], [%1], 16;\n" :: "r"(s), "l"(gsrc));
}
__device__ __forceinline__ void cp_commit() { asm volatile("cp.async.commit_group;\n"); }
__device__ __forceinline__ void cp_wait0()  { asm volatile("cp.async.wait_group 0;\n"); }
__device__ __forceinline__ void cp_wait1()  { asm volatile("cp.async.wait_group 1;\n"); }

// ---------------- fp32 -> bf16 convert ----------------
__global__ __launch_bounds__(256)
void convert_f2b(const float* __restrict__ src, bf16* __restrict__ dst, int n4)
{
    const int i = blockIdx.x * 256 + threadIdx.x;
    if (i < n4) {
        const float4 v = ((const float4*)src)[i];
        __nv_bfloat162 lo = __floats2bfloat162_rn(v.x, v.y);
        __nv_bfloat162 hi = __floats2bfloat162_rn(v.z, v.w);
        uint2 o;
        o.x = *(uint32_t*)&lo; o.y = *(uint32_t*)&hi;
        ((uint2*)dst)[i] = o;
    }
}

// ---------------- bf16 tensor-core GEMM, 3-stage cp.async pipeline ----------------
// C[M x N] = act( A * B + bias ); A,B bf16, fp32 accumulate.
// MODE_A: 0 = A row-major (M x K); 1 = A stored (K x M) -> logical A^T;
//         2 = split A: k<Ksplit from A, else A2 (row-major, same lda)
// TRANSB: 0 = B row-major (K x N); 1 = B stored (N x K) -> logical B^T
// ROWSUM: instead of writing C, sum act(row) over the block's 128 rows and
//         atomicAdd into Rout[batch*D + n]; batch = m0 / ldc (ldc carries L).
// Tiles: BM=BN=128, BK=32; 256 threads (8 warps); warp tile 32x64.

template <int MODE_A, int TRANSB, bool OUT_BF16, bool BIAS_RELU, bool ROWSUM>
__global__ __launch_bounds__(256)
void bgemm(const bf16* __restrict__ A, const bf16* __restrict__ A2,
           const bf16* __restrict__ Bm, const float* __restrict__ bias,
           void* __restrict__ C,
           int K, int Ksplit,
           int lda, int ldb, int ldc,
           long long sA, long long sB, long long sC)
{
    constexpr int BM = 128, BN = 128, BK = 32, NS = 3;
    constexpr int A_LD = (MODE_A == 1) ? (BM + 8) : (BK + 8);
    constexpr int ASZ  = (MODE_A == 1) ? BK * (BM + 8) : BM * (BK + 8);
    constexpr int B_LD = (TRANSB == 1) ? (BK + 8) : (BN + 8);
    constexpr int BSZ  = (TRANSB == 1) ? BN * (BK + 8) : BK * (BN + 8);
    constexpr int STAGE = ASZ + BSZ;       // bf16 elements
    constexpr int C_LD = BN + 4;           // fp32 epilogue staging

    extern __shared__ __align__(16) char smraw[];
    bf16* smb = (bf16*)smraw;

    const int bz = blockIdx.z;
    const bf16* Ab = A  + (long long)bz * sA;
    const bf16* Bb = Bm + (long long)bz * sB;

    const int tid  = threadIdx.x;
    const int warp = tid >> 5;
    const int wm   = warp >> 1;
    const int wn   = warp & 1;
    const int m0   = blockIdx.x * BM;
    const int n0   = blockIdx.y * BN;

    using ALayout = typename std::conditional<MODE_A == 1, wmma::col_major, wmma::row_major>::type;
    using BLayout = typename std::conditional<TRANSB == 1, wmma::col_major, wmma::row_major>::type;

    wmma::fragment<wmma::accumulator, 16, 16, 16, float> acc[2][4];
    #pragma unroll
    for (int i = 0; i < 2; i++)
        #pragma unroll
        for (int j = 0; j < 4; j++)
            wmma::fill_fragment(acc[i][j], 0.0f);

    auto load_stage = [&](int s, int k0) {
        bf16* As = smb + s * STAGE;
        bf16* Bs = As + ASZ;
        #pragma unroll
        for (int it = 0; it < 2; it++) {
            const int cch = tid + it * 256;
            if (MODE_A == 1) {
                const int k  = cch >> 4;
                const int mb = (cch & 15) * 8;
                cp_async16(&As[k * A_LD + mb], Ab + (long long)(k0 + k) * lda + m0 + mb);
            } else {
                const bf16* Asrc = Ab;
                int kk = k0;
                if (MODE_A == 2 && k0 >= Ksplit) { Asrc = A2; kk = k0 - Ksplit; }
                const int r  = cch >> 2;
                const int kb = (cch & 3) * 8;
                cp_async16(&As[r * A_LD + kb], Asrc + (long long)(m0 + r) * lda + kk + kb);
            }
        }
        #pragma unroll
        for (int it = 0; it < 2; it++) {
            const int cch = tid + it * 256;
            if (TRANSB == 1) {
                const int n  = cch >> 2;
                const int kb = (cch & 3) * 8;
                cp_async16(&Bs[n * B_LD + kb], Bb + (long long)(n0 + n) * ldb + k0 + kb);
            } else {
                const int k  = cch >> 4;
                const int nb = (cch & 15) * 8;
                cp_async16(&Bs[k * B_LD + nb], Bb + (long long)(k0 + k) * ldb + n0 + nb);
            }
        }
    };

    const int nT = K / BK;
    #pragma unroll
    for (int s = 0; s < NS - 1; s++) { load_stage(s, s * BK); cp_commit(); }

    for (int t = 0; t < nT; t++) {
        if (t + 1 < nT) cp_wait1(); else cp_wait0();
        __syncthreads();
        if (t + NS - 1 < nT) { load_stage((t + NS - 1) % NS, (t + NS - 1) * BK); cp_commit(); }

        const bf16* As = smb + (t % NS) * STAGE;
        const bf16* Bs = As + ASZ;
        #pragma unroll
        for (int kk = 0; kk < BK; kk += 16) {
            wmma::fragment<wmma::matrix_a, 16, 16, 16, bf16, ALayout> afr[2];
            wmma::fragment<wmma::matrix_b, 16, 16, 16, bf16, BLayout> bfr[4];
            #pragma unroll
            for (int i = 0; i < 2; i++) {
                const int row = wm * 32 + i * 16;
                const bf16* p = (MODE_A == 1) ? &As[kk * A_LD + row]
                                              : &As[row * A_LD + kk];
                wmma::load_matrix_sync(afr[i], p, A_LD);
            }
            #pragma unroll
            for (int j = 0; j < 4; j++) {
                const int col = wn * 64 + j * 16;
                const bf16* p = (TRANSB == 1) ? &Bs[col * B_LD + kk]
                                              : &Bs[kk * B_LD + col];
                wmma::load_matrix_sync(bfr[j], p, B_LD);
            }
            #pragma unroll
            for (int i = 0; i < 2; i++)
                #pragma unroll
                for (int j = 0; j < 4; j++)
                    wmma::mma_sync(acc[i][j], afr[i], bfr[j], acc[i][j]);
        }
        __syncthreads();
    }

    // ---- epilogue ----
    float* Cs = (float*)smraw;
    const int lane = tid & 31;
    float4 bb = make_float4(0.f, 0.f, 0.f, 0.f);
    if (BIAS_RELU) bb = *(const float4*)&bias[n0 + lane * 4];

    float csum[4] = {0.f, 0.f, 0.f, 0.f};

    #pragma unroll
    for (int phase = 0; phase < 2; phase++) {
        if ((warp < 4) == (phase == 0)) {
            const int rbase = (wm & 1) * 32;
            #pragma unroll
            for (int i = 0; i < 2; i++)
                #pragma unroll
                for (int j = 0; j < 4; j++)
                    wmma::store_matrix_sync(&Cs[(rbase + i * 16) * C_LD + wn * 64 + j * 16],
                                            acc[i][j], C_LD, wmma::mem_row_major);
        }
        __syncthreads();
        #pragma unroll
        for (int it = 0; it < 8; it++) {
            const int r = it * 8 + warp;
            float4 v = *(float4*)&Cs[r * C_LD + lane * 4];
            if (BIAS_RELU) {
                v.x = fmaxf(v.x + bb.x, 0.f); v.y = fmaxf(v.y + bb.y, 0.f);
                v.z = fmaxf(v.z + bb.z, 0.f); v.w = fmaxf(v.w + bb.w, 0.f);
            }
            if (ROWSUM) {
                csum[0] += v.x; csum[1] += v.y; csum[2] += v.z; csum[3] += v.w;
            } else {
                const long long row = (long long)(m0 + phase * 64 + r);
                if (OUT_BF16) {
                    bf16* Cb = (bf16*)C + (long long)bz * sC;
                    __nv_bfloat162 lo = __floats2bfloat162_rn(v.x, v.y);
                    __nv_bfloat162 hi = __floats2bfloat162_rn(v.z, v.w);
                    uint2 o; o.x = *(uint32_t*)&lo; o.y = *(uint32_t*)&hi;
                    *(uint2*)(Cb + row * ldc + n0 + lane * 4) = o;
                } else {
                    float* Cb = (float*)C + (long long)bz * sC;
                    *(float4*)(Cb + row * ldc + n0 + lane * 4) = v;
                }
            }
        }
        __syncthreads();
    }

    if (ROWSUM) {
        // per-warp partial (each warp summed 16 distinct rows for all 128 cols)
        *(float4*)&Cs[warp * 128 + lane * 4] = make_float4(csum[0], csum[1], csum[2], csum[3]);
        __syncthreads();
        if (tid < 128) {
            float s = 0.f;
            #pragma unroll
            for (int w = 0; w < 8; w++) s += Cs[w * 128 + tid];
            const int batch = m0 / ldc;                   // ldc carries L
            atomicAdd((float*)C + batch * D_ + n0 + tid, s);
        }
    }
}

// ---------------- masked softmax over Le (rows) -> bf16 alpha ----------------
__global__ __launch_bounds__(256)
void softmax_rows(const float* __restrict__ align, const int* __restrict__ emask,
                  bf16* __restrict__ out)
{
    const int row = blockIdx.x;
    const int b = row >> 8;
    const float* a = align + (long long)row * LE;
    bf16* o = out + (long long)row * LE;
    const int* em = emask + b * LE;
    const int t = threadIdx.x;

    float vals[4];
    float mx = -3.4e38f;
    #pragma unroll
    for (int i = 0; i < 4; i++) {
        const int e = t + i * 256;
        float v = a[e] + (1.0f - (float)em[e]) * NEGV;
        vals[i] = v;
        mx = fmaxf(mx, v);
    }
    __shared__ float red[256];
    red[t] = mx; __syncthreads();
    for (int s = 128; s > 0; s >>= 1) {
        if (t < s) red[t] = fmaxf(red[t], red[t + s]);
        __syncthreads();
    }
    mx = red[0]; __syncthreads();

    float sum = 0.f;
    #pragma unroll
    for (int i = 0; i < 4; i++) { vals[i] = __expf(vals[i] - mx); sum += vals[i]; }
    red[t] = sum; __syncthreads();
    for (int s = 128; s > 0; s >>= 1) {
        if (t < s) red[t] += red[t + s];
        __syncthreads();
    }
    const float inv = 1.0f / red[0];
    #pragma unroll
    for (int i = 0; i < 4; i++) o[t + i * 256] = __float2bfloat16(vals[i] * inv);
}

// ---------------- masked softmax over Lc (columns) -> bf16 beta (online, 2 passes) ----
__global__ __launch_bounds__(256)
void softmax_cols(const float* __restrict__ align, const int* __restrict__ cmask,
                  bf16* __restrict__ out)
{
    __shared__ float cmsk[LC];
    const int b = blockIdx.y;
    const int e = blockIdx.x * 256 + threadIdx.x;
    const float* a = align + (long long)b * LC * LE + e;
    bf16* o = out + (long long)b * LC * LE + e;
    const int* cm = cmask + b * LC;
    cmsk[threadIdx.x] = (1.0f - (float)cm[threadIdx.x]) * NEGV;
    __syncthreads();

    // pass 1: online max + rescaled sum
    float mx = -3.4e38f, sum = 0.f;
    #pragma unroll 4
    for (int l = 0; l < LC; l++) {
        const float v = a[(long long)l * LE] + cmsk[l];
        if (v > mx) { sum = sum * __expf(mx - v); mx = v; }
        sum += __expf(v - mx);
    }
    const float inv = 1.0f / sum;
    // pass 2: write
    #pragma unroll 4
    for (int l = 0; l < LC; l++)
        o[(long long)l * LE] = __float2bfloat16(__expf(a[(long long)l * LE] + cmsk[l] - mx) * inv);
}

// ---------------- final MLP: one block per batch ----------------
__global__ __launch_bounds__(256)
void final_mlp(const float* __restrict__ r1, const float* __restrict__ r2,
               const float* __restrict__ Wm, const float* __restrict__ bm,
               const float* __restrict__ Wo, const float* __restrict__ bo,
               float* __restrict__ out)
{
    const int b = blockIdx.x;
    const int t = threadIdx.x;
    __shared__ float m[4 * D_];
    __shared__ float h[M_];

    const float a = r1[b * D_ + t];
    const float c = r2[b * D_ + t];
    m[t] = a; m[D_ + t] = c; m[2 * D_ + t] = a * c; m[3 * D_ + t] = a - c;
    __syncthreads();

    for (int j = t; j < M_; j += 256) {
        float s = bm[j];
        #pragma unroll 8
        for (int k = 0; k < 4 * D_; k++) s += m[k] * Wm[k * M_ + j];
        h[j] = fmaxf(s, 0.f);
    }
    __syncthreads();

    float p0 = 0.f, p1 = 0.f, p2 = 0.f;
    for (int j = t; j < M_; j += 256) {
        const float hv = h[j];
        p0 += hv * Wo[j * 3 + 0];
        p1 += hv * Wo[j * 3 + 1];
        p2 += hv * Wo[j * 3 + 2];
    }
    __shared__ float red[3][256];
    red[0][t] = p0; red[1][t] = p1; red[2][t] = p2; __syncthreads();
    for (int s = 128; s > 0; s >>= 1) {
        if (t < s) {
            red[0][t] += red[0][t + s];
            red[1][t] += red[1][t + s];
            red[2][t] += red[2][t + s];
        }
        __syncthreads();
    }
    if (t < 3) out[b * 3 + t] = red[t][0] + bo[t];
}

// ---------------- host launcher ----------------
static const int GSMEM = 64 * 1024;

extern "C" void kernel_launch(void* const* d_in, const int* in_sizes, int n_in,
                              void* d_out, int out_size)
{
    const float *criteria = nullptr, *ehr = nullptr, *Wa = nullptr, *ba = nullptr,
                *Wr = nullptr, *br = nullptr, *Wm = nullptr, *bm = nullptr,
                *Wo = nullptr, *bo = nullptr;
    const int *cmask = nullptr, *emask = nullptr;

    for (int i = 0; i < n_in; i++) {
        const int s = in_sizes[i];
        switch (s) {
            case 8388608:  criteria = (const float*)d_in[i]; break;
            case 33554432: ehr      = (const float*)d_in[i]; break;
            case 32768:    cmask    = (const int*)d_in[i];   break;
            case 65536:    Wa       = (const float*)d_in[i]; break;
            case 524288:   Wm       = (const float*)d_in[i]; break;
            case 512:      bm       = (const float*)d_in[i]; break;
            case 1536:     Wo       = (const float*)d_in[i]; break;
            case 3:        bo       = (const float*)d_in[i]; break;
            case 131072: {
                const int prev = (i > 0) ? in_sizes[i - 1] : -1;
                if (prev == 256) Wr = (const float*)d_in[i];
                else             emask = (const int*)d_in[i];
                break;
            }
            case 256: {
                const int nxt = (i + 1 < n_in) ? in_sizes[i + 1] : -1;
                if (nxt == 131072) ba = (const float*)d_in[i];
                else               br = (const float*)d_in[i];
                break;
            }
            default: break;
        }
    }

    cudaFuncSetAttribute(bgemm<0,0,true,true,false>,  cudaFuncAttributeMaxDynamicSharedMemorySize, GSMEM);
    cudaFuncSetAttribute(bgemm<0,1,false,false,false>,cudaFuncAttributeMaxDynamicSharedMemorySize, GSMEM);
    cudaFuncSetAttribute(bgemm<0,0,true,false,false>, cudaFuncAttributeMaxDynamicSharedMemorySize, GSMEM);
    cudaFuncSetAttribute(bgemm<1,0,true,false,false>, cudaFuncAttributeMaxDynamicSharedMemorySize, GSMEM);
    cudaFuncSetAttribute(bgemm<2,0,false,true,true>,  cudaFuncAttributeMaxDynamicSharedMemorySize, GSMEM);

    float *al_, *r1_, *r2_;
    bf16 *crb, *ehb, *Wab, *Wrb, *cb, *eb, *alb, *beb, *atcb, *ateb;
    cudaGetSymbolAddress((void**)&al_,  g_align);
    cudaGetSymbolAddress((void**)&r1_,  g_r1);
    cudaGetSymbolAddress((void**)&r2_,  g_r2);
    cudaGetSymbolAddress((void**)&crb,  g_crb);
    cudaGetSymbolAddress((void**)&ehb,  g_ehb);
    cudaGetSymbolAddress((void**)&Wab,  g_Wab);
    cudaGetSymbolAddress((void**)&Wrb,  g_Wrb);
    cudaGetSymbolAddress((void**)&cb,   g_cb);
    cudaGetSymbolAddress((void**)&eb,   g_eb);
    cudaGetSymbolAddress((void**)&alb,  g_alb);
    cudaGetSymbolAddress((void**)&beb,  g_beb);
    cudaGetSymbolAddress((void**)&atcb, g_atcb);
    cudaGetSymbolAddress((void**)&ateb, g_ateb);

    const dim3 blk(256);

    // 0) fp32 -> bf16 conversions + zero accumulators
    convert_f2b<<<(B_*LC*D_/4 + 255)/256, 256>>>(criteria, crb, B_*LC*D_/4);
    convert_f2b<<<(B_*LE*D_/4 + 255)/256, 256>>>(ehr,      ehb, B_*LE*D_/4);
    convert_f2b<<<(D_*D_/4   + 255)/256, 256>>>(Wa,       Wab, D_*D_/4);
    convert_f2b<<<(2*D_*D_/4 + 255)/256, 256>>>(Wr,       Wrb, 2*D_*D_/4);
    cudaMemsetAsync(r1_, 0, B_ * D_ * sizeof(float));
    cudaMemsetAsync(r2_, 0, B_ * D_ * sizeof(float));

    // 1) c = relu(criteria@Wa+ba) -> bf16
    bgemm<0, 0, true, true, false><<<dim3(256, 2, 1), blk, GSMEM>>>(
        crb, nullptr, Wab, ba, cb, D_, 0, D_, D_, D_, 0, 0, 0);
    // 2) e = relu(ehr@Wa+ba) -> bf16
    bgemm<0, 0, true, true, false><<<dim3(1024, 2, 1), blk, GSMEM>>>(
        ehb, nullptr, Wab, ba, eb, D_, 0, D_, D_, D_, 0, 0, 0);
    // 3) align[b] = c[b] @ e[b]^T -> fp32, batched
    bgemm<0, 1, false, false, false><<<dim3(2, 8, B_), blk, GSMEM>>>(
        cb, nullptr, eb, nullptr, al_, D_, 0, D_, D_, LE,
        (long long)LC * D_, (long long)LE * D_, (long long)LC * LE);
    // 4) alpha = softmax over Le (rows) -> bf16
    softmax_rows<<<B_ * LC, 256>>>(al_, emask, alb);
    // 5) beta = softmax over Lc (columns) -> bf16
    softmax_cols<<<dim3(LE / 256, B_), 256>>>(al_, cmask, beb);
    // 6) att_c[b] = alpha[b] @ ehr[b] -> bf16
    bgemm<0, 0, true, false, false><<<dim3(2, 2, B_), blk, GSMEM>>>(
        alb, nullptr, ehb, nullptr, atcb, LE, 0, LE, D_, D_,
        (long long)LC * LE, (long long)LE * D_, (long long)LC * D_);
    // 7) att_e[b] = beta[b]^T @ criteria[b] -> bf16
    bgemm<1, 0, true, false, false><<<dim3(8, 2, B_), blk, GSMEM>>>(
        beb, nullptr, crb, nullptr, ateb, LC, 0, LE, D_, D_,
        (long long)LC * LE, (long long)LC * D_, (long long)LE * D_);
    // 8) r1 += rowsum(relu([att_c|criteria]@Wr+br)) fused; ldc carries L=LC
    bgemm<2, 0, false, true, true><<<dim3(256, 2, 1), blk, GSMEM>>>(
        atcb, crb, Wrb, br, r1_, 2 * D_, D_, D_, D_, LC, 0, 0, 0);
    // 9) r2 += rowsum(relu([att_e|ehr]@Wr+br)) fused; ldc carries L=LE
    bgemm<2, 0, false, true, true><<<dim3(1024, 2, 1), blk, GSMEM>>>(
        ateb, ehb, Wrb, br, r2_, 2 * D_, D_, D_, D_, LE, 0, 0, 0);
    // 10) final MLP -> (B, 3)
    final_mlp<<<B_, 256>>>(r1_, r2_, Wm, bm, Wo, bo, (float*)d_out);
}

// round 13
// speedup vs baseline: 5.4212x; 1.0794x over previous
#include <cuda_runtime.h>
#include <cuda_bf16.h>
#include <mma.h>
#include <cstdint>
#include <type_traits>

using namespace nvcuda;

#define B_  128
#define LC  256
#define LE  1024
#define D_  256
#define M_  512
#define NEGV (-1e9f)

typedef __nv_bfloat16 bf16;

// ---------------- scratch (device globals; no allocs allowed) ----------------
__device__ float g_align[(size_t)B_ * LC * LE];   // align (pre-softmax), fp32
__device__ float g_r1   [B_ * D_];
__device__ float g_r2   [B_ * D_];
__device__ bf16 g_crb  [(size_t)B_ * LC * D_];    // criteria bf16
__device__ bf16 g_ehb  [(size_t)B_ * LE * D_];    // ehr bf16
__device__ bf16 g_Wab  [D_ * D_];
__device__ bf16 g_Wrb  [2 * D_ * D_];
__device__ bf16 g_cb   [(size_t)B_ * LC * D_];    // relu(criteria@Wa+ba)
__device__ bf16 g_eb   [(size_t)B_ * LE * D_];    // relu(ehr@Wa+ba)
__device__ bf16 g_alb  [(size_t)B_ * LC * LE];    // alpha (Lc,Le)
__device__ bf16 g_bebT [(size_t)B_ * LE * LC];    // beta^T (Le,Lc)
__device__ bf16 g_atcb [(size_t)B_ * LC * D_];    // att_c
__device__ bf16 g_ateb [(size_t)B_ * LE * D_];    // att_e

__device__ __forceinline__ void cp_async16(void* smem_dst, const void* gsrc) {
    const uint32_t s = (uint32_t)__cvta_generic_to_shared(smem_dst);
    asm volatile("cp.async.cg.shared.global [%0], [%1], 16;\n" :: "r"(s), "l"(gsrc));
}
__device__ __forceinline__ void cp_commit() { asm volatile("cp.async.commit_group;\n"); }
__device__ __forceinline__ void cp_wait0()  { asm volatile("cp.async.wait_group 0;\n"); }
__device__ __forceinline__ void cp_wait1()  { asm volatile("cp.async.wait_group 1;\n"); }

// ---------------- fp32 -> bf16 convert ----------------
__global__ __launch_bounds__(256)
void convert_f2b(const float* __restrict__ src, bf16* __restrict__ dst, int n4)
{
    const int i = blockIdx.x * 256 + threadIdx.x;
    if (i < n4) {
        const float4 v = ((const float4*)src)[i];
        __nv_bfloat162 lo = __floats2bfloat162_rn(v.x, v.y);
        __nv_bfloat162 hi = __floats2bfloat162_rn(v.z, v.w);
        uint2 o;
        o.x = *(uint32_t*)&lo; o.y = *(uint32_t*)&hi;
        ((uint2*)dst)[i] = o;
    }
}

// ---------------- bf16 wmma GEMM: 128 threads, 4 warps, warp tile 64x64 --------
// C[M x N] = act( A * B + bias ); A,B bf16, fp32 accumulate.
// A row-major (M x K), SPLITA: k<Ksplit from A else A2 (row-major, same lda).
// TRANSB: 0 = B row-major (K x N), 1 = B stored (N x K) -> logical B^T.
// ROWSUM: atomicAdd col-sums of act(C-rows) into Rout[batch*D + n], batch = m0/Lrows.
// Tiles: BM=BN=128, BK=32, 3-stage cp.async.

template <bool SPLITA, int TRANSB, bool OUT_BF16, bool BIAS_RELU, bool ROWSUM>
__global__ __launch_bounds__(128)
void bgemm(const bf16* __restrict__ A, const bf16* __restrict__ A2,
           const bf16* __restrict__ Bm, const float* __restrict__ bias,
           void* __restrict__ C,
           int K, int Ksplit,
           int lda, int ldb, int ldc,
           long long sA, long long sB, long long sC, int Lrows)
{
    constexpr int BM = 128, BN = 128, BK = 32, NS = 3;
    constexpr int A_LD = BK + 8;                                // 40
    constexpr int ASZ  = BM * A_LD;                             // 5120
    constexpr int B_LD = (TRANSB == 1) ? (BK + 8) : (BN + 8);   // 40 : 136
    constexpr int BSZ  = (TRANSB == 1) ? BN * (BK + 8) : BK * (BN + 8);
    constexpr int STAGE = ASZ + BSZ;                            // bf16 elements
    constexpr int C_LD = BN + 4;                                // 132 (fp32 staging)

    extern __shared__ __align__(16) char smraw[];
    bf16* smb = (bf16*)smraw;

    const int bz = blockIdx.z;
    const bf16* Ab = A  + (long long)bz * sA;
    const bf16* Bb = Bm + (long long)bz * sB;

    const int tid  = threadIdx.x;
    const int warp = tid >> 5;
    const int wm   = warp >> 1;      // 0..1 -> 64-row group
    const int wn   = warp & 1;       // 0..1 -> 64-col group
    const int m0   = blockIdx.x * BM;
    const int n0   = blockIdx.y * BN;

    using BLayout = typename std::conditional<TRANSB == 1, wmma::col_major, wmma::row_major>::type;

    wmma::fragment<wmma::accumulator, 16, 16, 16, float> acc[4][4];
    #pragma unroll
    for (int i = 0; i < 4; i++)
        #pragma unroll
        for (int j = 0; j < 4; j++)
            wmma::fill_fragment(acc[i][j], 0.0f);

    auto load_stage = [&](int s, int k0) {
        bf16* As = smb + s * STAGE;
        bf16* Bs = As + ASZ;
        const bf16* Asrc = Ab;
        int kk = k0;
        if (SPLITA && k0 >= Ksplit) { Asrc = A2; kk = k0 - Ksplit; }
        #pragma unroll
        for (int it = 0; it < 4; it++) {            // A: 512 chunks of 16B
            const int idx = tid + it * 128;
            const int r  = idx >> 2;
            const int kb = (idx & 3) * 8;
            cp_async16(&As[r * A_LD + kb], Asrc + (long long)(m0 + r) * lda + kk + kb);
        }
        #pragma unroll
        for (int it = 0; it < 4; it++) {            // B: 512 chunks of 16B
            const int idx = tid + it * 128;
            if (TRANSB == 1) {
                const int n  = idx >> 2;
                const int kb = (idx & 3) * 8;
                cp_async16(&Bs[n * B_LD + kb], Bb + (long long)(n0 + n) * ldb + k0 + kb);
            } else {
                const int k  = idx >> 4;
                const int nb = (idx & 15) * 8;
                cp_async16(&Bs[k * B_LD + nb], Bb + (long long)(k0 + k) * ldb + n0 + nb);
            }
        }
    };

    const int nT = K / BK;
    #pragma unroll
    for (int s = 0; s < NS - 1; s++) { load_stage(s, s * BK); cp_commit(); }

    for (int t = 0; t < nT; t++) {
        if (t + 1 < nT) cp_wait1(); else cp_wait0();
        __syncthreads();
        if (t + NS - 1 < nT) { load_stage((t + NS - 1) % NS, (t + NS - 1) * BK); cp_commit(); }

        const bf16* As = smb + (t % NS) * STAGE;
        const bf16* Bs = As + ASZ;
        #pragma unroll
        for (int kk = 0; kk < BK; kk += 16) {
            wmma::fragment<wmma::matrix_a, 16, 16, 16, bf16, wmma::row_major> afr[4];
            wmma::fragment<wmma::matrix_b, 16, 16, 16, bf16, BLayout> bfr[4];
            #pragma unroll
            for (int i = 0; i < 4; i++) {
                const int row = wm * 64 + i * 16;
                wmma::load_matrix_sync(afr[i], &As[row * A_LD + kk], A_LD);
            }
            #pragma unroll
            for (int j = 0; j < 4; j++) {
                const int col = wn * 64 + j * 16;
                const bf16* p = (TRANSB == 1) ? &Bs[col * B_LD + kk]
                                              : &Bs[kk * B_LD + col];
                wmma::load_matrix_sync(bfr[j], p, B_LD);
            }
            #pragma unroll
            for (int i = 0; i < 4; i++)
                #pragma unroll
                for (int j = 0; j < 4; j++)
                    wmma::mma_sync(acc[i][j], afr[i], bfr[j], acc[i][j]);
        }
        __syncthreads();
    }

    // ---- epilogue: 2 phases of 64 rows via fp32 smem staging ----
    float* Cs = (float*)smraw;
    const int c4 = tid & 31;                         // fixed float4 column per thread
    float4 bb = make_float4(0.f, 0.f, 0.f, 0.f);
    if (BIAS_RELU) bb = *(const float4*)&bias[n0 + c4 * 4];

    float csum[4] = {0.f, 0.f, 0.f, 0.f};

    #pragma unroll
    for (int phase = 0; phase < 2; phase++) {
        if (wm == phase) {
            #pragma unroll
            for (int i = 0; i < 4; i++)
                #pragma unroll
                for (int j = 0; j < 4; j++)
                    wmma::store_matrix_sync(&Cs[(i * 16) * C_LD + wn * 64 + j * 16],
                                            acc[i][j], C_LD, wmma::mem_row_major);
        }
        __syncthreads();
        #pragma unroll
        for (int it = 0; it < 16; it++) {
            const int idx = it * 128 + tid;
            const int r = idx >> 5;                  // 0..63
            float4 v = *(float4*)&Cs[r * C_LD + c4 * 4];
            if (BIAS_RELU) {
                v.x = fmaxf(v.x + bb.x, 0.f); v.y = fmaxf(v.y + bb.y, 0.f);
                v.z = fmaxf(v.z + bb.z, 0.f); v.w = fmaxf(v.w + bb.w, 0.f);
            }
            if (ROWSUM) {
                csum[0] += v.x; csum[1] += v.y; csum[2] += v.z; csum[3] += v.w;
            } else {
                const long long row = (long long)(m0 + phase * 64 + r);
                if (OUT_BF16) {
                    bf16* Cb = (bf16*)C + (long long)bz * sC;
                    __nv_bfloat162 lo = __floats2bfloat162_rn(v.x, v.y);
                    __nv_bfloat162 hi = __floats2bfloat162_rn(v.z, v.w);
                    uint2 o; o.x = *(uint32_t*)&lo; o.y = *(uint32_t*)&hi;
                    *(uint2*)(Cb + row * ldc + n0 + c4 * 4) = o;
                } else {
                    float* Cb = (float*)C + (long long)bz * sC;
                    *(float4*)(Cb + row * ldc + n0 + c4 * 4) = v;
                }
            }
        }
        __syncthreads();
    }

    if (ROWSUM) {
        *(float4*)&Cs[tid * 4] = make_float4(csum[0], csum[1], csum[2], csum[3]);
        __syncthreads();
        if (tid < 32) {
            const int batch = m0 / Lrows;
            float* dst = (float*)C + batch * D_ + n0 + tid * 4;
            #pragma unroll
            for (int k = 0; k < 4; k++) {
                const float s = Cs[tid * 4 + k] + Cs[(tid + 32) * 4 + k]
                              + Cs[(tid + 64) * 4 + k] + Cs[(tid + 96) * 4 + k];
                atomicAdd(dst + k, s);
            }
        }
    }
}

// ---------------- masked softmax over Le (rows) -> bf16 alpha ----------------
__global__ __launch_bounds__(256)
void softmax_rows(const float* __restrict__ align, const int* __restrict__ emask,
                  bf16* __restrict__ out)
{
    const int row = blockIdx.x;
    const int b = row >> 8;
    const float* a = align + (long long)row * LE;
    bf16* o = out + (long long)row * LE;
    const int* em = emask + b * LE;
    const int t = threadIdx.x;

    float vals[4];
    float mx = -3.4e38f;
    #pragma unroll
    for (int i = 0; i < 4; i++) {
        const int e = t + i * 256;
        float v = a[e] + (1.0f - (float)em[e]) * NEGV;
        vals[i] = v;
        mx = fmaxf(mx, v);
    }
    __shared__ float red[256];
    red[t] = mx; __syncthreads();
    for (int s = 128; s > 0; s >>= 1) {
        if (t < s) red[t] = fmaxf(red[t], red[t + s]);
        __syncthreads();
    }
    mx = red[0]; __syncthreads();

    float sum = 0.f;
    #pragma unroll
    for (int i = 0; i < 4; i++) { vals[i] = __expf(vals[i] - mx); sum += vals[i]; }
    red[t] = sum; __syncthreads();
    for (int s = 128; s > 0; s >>= 1) {
        if (t < s) red[t] += red[t + s];
        __syncthreads();
    }
    const float inv = 1.0f / red[0];
    #pragma unroll
    for (int i = 0; i < 4; i++) o[t + i * 256] = __float2bfloat16(vals[i] * inv);
}

// ---------------- masked softmax over Lc (cols) -> bf16 beta^T (Le,Lc) --------
__global__ __launch_bounds__(256)
void softmax_colsT(const float* __restrict__ align, const int* __restrict__ cmask,
                   bf16* __restrict__ outT)
{
    __shared__ float cmsk[LC];
    const int b = blockIdx.y;
    const int e = blockIdx.x * 256 + threadIdx.x;
    const float* a = align + (long long)b * LC * LE + e;
    bf16* o = outT + (long long)b * LE * LC + (long long)e * LC;   // row e of beta^T
    const int* cm = cmask + b * LC;
    cmsk[threadIdx.x] = (1.0f - (float)cm[threadIdx.x]) * NEGV;
    __syncthreads();

    float mx = -3.4e38f, sum = 0.f;
    #pragma unroll 4
    for (int l = 0; l < LC; l++) {
        const float v = a[(long long)l * LE] + cmsk[l];
        if (v > mx) { sum = sum * __expf(mx - v); mx = v; }
        sum += __expf(v - mx);
    }
    const float inv = 1.0f / sum;
    for (int l0 = 0; l0 < LC; l0 += 8) {
        uint32_t pk[4];
        #pragma unroll
        for (int j = 0; j < 4; j++) {
            const float v0 = __expf(a[(long long)(l0 + 2*j    ) * LE] + cmsk[l0 + 2*j    ] - mx) * inv;
            const float v1 = __expf(a[(long long)(l0 + 2*j + 1) * LE] + cmsk[l0 + 2*j + 1] - mx) * inv;
            __nv_bfloat162 h = __floats2bfloat162_rn(v0, v1);
            pk[j] = *(uint32_t*)&h;
        }
        *(uint4*)(o + l0) = make_uint4(pk[0], pk[1], pk[2], pk[3]);
    }
}

// ---------------- final MLP: one block per batch ----------------
__global__ __launch_bounds__(256)
void final_mlp(const float* __restrict__ r1, const float* __restrict__ r2,
               const float* __restrict__ Wm, const float* __restrict__ bm,
               const float* __restrict__ Wo, const float* __restrict__ bo,
               float* __restrict__ out)
{
    const int b = blockIdx.x;
    const int t = threadIdx.x;
    __shared__ float m[4 * D_];
    __shared__ float h[M_];

    const float a = r1[b * D_ + t];
    const float c = r2[b * D_ + t];
    m[t] = a; m[D_ + t] = c; m[2 * D_ + t] = a * c; m[3 * D_ + t] = a - c;
    __syncthreads();

    for (int j = t; j < M_; j += 256) {
        float s = bm[j];
        #pragma unroll 8
        for (int k = 0; k < 4 * D_; k++) s += m[k] * Wm[k * M_ + j];
        h[j] = fmaxf(s, 0.f);
    }
    __syncthreads();

    float p0 = 0.f, p1 = 0.f, p2 = 0.f;
    for (int j = t; j < M_; j += 256) {
        const float hv = h[j];
        p0 += hv * Wo[j * 3 + 0];
        p1 += hv * Wo[j * 3 + 1];
        p2 += hv * Wo[j * 3 + 2];
    }
    __shared__ float red[3][256];
    red[0][t] = p0; red[1][t] = p1; red[2][t] = p2; __syncthreads();
    for (int s = 128; s > 0; s >>= 1) {
        if (t < s) {
            red[0][t] += red[0][t + s];
            red[1][t] += red[1][t + s];
            red[2][t] += red[2][t + s];
        }
        __syncthreads();
    }
    if (t < 3) out[b * 3 + t] = red[t][0] + bo[t];
}

// ---------------- host launcher ----------------
static const int GSMEM = 62 * 1024;   // 3 stages x 20.0KB max + epilogue staging 33.8KB

extern "C" void kernel_launch(void* const* d_in, const int* in_sizes, int n_in,
                              void* d_out, int out_size)
{
    const float *criteria = nullptr, *ehr = nullptr, *Wa = nullptr, *ba = nullptr,
                *Wr = nullptr, *br = nullptr, *Wm = nullptr, *bm = nullptr,
                *Wo = nullptr, *bo = nullptr;
    const int *cmask = nullptr, *emask = nullptr;

    for (int i = 0; i < n_in; i++) {
        const int s = in_sizes[i];
        switch (s) {
            case 8388608:  criteria = (const float*)d_in[i]; break;
            case 33554432: ehr      = (const float*)d_in[i]; break;
            case 32768:    cmask    = (const int*)d_in[i];   break;
            case 65536:    Wa       = (const float*)d_in[i]; break;
            case 524288:   Wm       = (const float*)d_in[i]; break;
            case 512:      bm       = (const float*)d_in[i]; break;
            case 1536:     Wo       = (const float*)d_in[i]; break;
            case 3:        bo       = (const float*)d_in[i]; break;
            case 131072: {
                const int prev = (i > 0) ? in_sizes[i - 1] : -1;
                if (prev == 256) Wr = (const float*)d_in[i];
                else             emask = (const int*)d_in[i];
                break;
            }
            case 256: {
                const int nxt = (i + 1 < n_in) ? in_sizes[i + 1] : -1;
                if (nxt == 131072) ba = (const float*)d_in[i];
                else               br = (const float*)d_in[i];
                break;
            }
            default: break;
        }
    }

    cudaFuncSetAttribute(bgemm<false,0,true,true,false>,  cudaFuncAttributeMaxDynamicSharedMemorySize, GSMEM);
    cudaFuncSetAttribute(bgemm<false,1,false,false,false>,cudaFuncAttributeMaxDynamicSharedMemorySize, GSMEM);
    cudaFuncSetAttribute(bgemm<false,0,true,false,false>, cudaFuncAttributeMaxDynamicSharedMemorySize, GSMEM);
    cudaFuncSetAttribute(bgemm<true,0,false,true,true>,   cudaFuncAttributeMaxDynamicSharedMemorySize, GSMEM);

    float *al_, *r1_, *r2_;
    bf16 *crb, *ehb, *Wab, *Wrb, *cb, *eb, *alb, *bebT, *atcb, *ateb;
    cudaGetSymbolAddress((void**)&al_,  g_align);
    cudaGetSymbolAddress((void**)&r1_,  g_r1);
    cudaGetSymbolAddress((void**)&r2_,  g_r2);
    cudaGetSymbolAddress((void**)&crb,  g_crb);
    cudaGetSymbolAddress((void**)&ehb,  g_ehb);
    cudaGetSymbolAddress((void**)&Wab,  g_Wab);
    cudaGetSymbolAddress((void**)&Wrb,  g_Wrb);
    cudaGetSymbolAddress((void**)&cb,   g_cb);
    cudaGetSymbolAddress((void**)&eb,   g_eb);
    cudaGetSymbolAddress((void**)&alb,  g_alb);
    cudaGetSymbolAddress((void**)&bebT, g_bebT);
    cudaGetSymbolAddress((void**)&atcb, g_atcb);
    cudaGetSymbolAddress((void**)&ateb, g_ateb);

    const dim3 blk(128);

    // 0) fp32 -> bf16 conversions + zero accumulators
    convert_f2b<<<(B_*LC*D_/4 + 255)/256, 256>>>(criteria, crb, B_*LC*D_/4);
    convert_f2b<<<(B_*LE*D_/4 + 255)/256, 256>>>(ehr,      ehb, B_*LE*D_/4);
    convert_f2b<<<(D_*D_/4   + 255)/256, 256>>>(Wa,       Wab, D_*D_/4);
    convert_f2b<<<(2*D_*D_/4 + 255)/256, 256>>>(Wr,       Wrb, 2*D_*D_/4);
    cudaMemsetAsync(r1_, 0, B_ * D_ * sizeof(float));
    cudaMemsetAsync(r2_, 0, B_ * D_ * sizeof(float));

    // 1) c = relu(criteria@Wa+ba) -> bf16
    bgemm<false,0,true,true,false><<<dim3(256, 2, 1), blk, GSMEM>>>(
        crb, nullptr, Wab, ba, cb, D_, 0, D_, D_, D_, 0, 0, 0, 0);
    // 2) e = relu(ehr@Wa+ba) -> bf16
    bgemm<false,0,true,true,false><<<dim3(1024, 2, 1), blk, GSMEM>>>(
        ehb, nullptr, Wab, ba, eb, D_, 0, D_, D_, D_, 0, 0, 0, 0);
    // 3) align[b] = c[b] @ e[b]^T -> fp32, batched
    bgemm<false,1,false,false,false><<<dim3(2, 8, B_), blk, GSMEM>>>(
        cb, nullptr, eb, nullptr, al_, D_, 0, D_, D_, LE,
        (long long)LC * D_, (long long)LE * D_, (long long)LC * LE, 0);
    // 4) alpha = softmax over Le (rows) -> bf16 (Lc,Le)
    softmax_rows<<<B_ * LC, 256>>>(al_, emask, alb);
    // 5) beta^T = softmax over Lc (cols) -> bf16 (Le,Lc)
    softmax_colsT<<<dim3(LE / 256, B_), 256>>>(al_, cmask, bebT);
    // 6) att_c[b] = alpha[b] @ ehr[b] -> bf16
    bgemm<false,0,true,false,false><<<dim3(2, 2, B_), blk, GSMEM>>>(
        alb, nullptr, ehb, nullptr, atcb, LE, 0, LE, D_, D_,
        (long long)LC * LE, (long long)LE * D_, (long long)LC * D_, 0);
    // 7) att_e[b] = beta^T[b] @ criteria[b] -> bf16 (A = betaT row-major)
    bgemm<false,0,true,false,false><<<dim3(8, 2, B_), blk, GSMEM>>>(
        bebT, nullptr, crb, nullptr, ateb, LC, 0, LC, D_, D_,
        (long long)LE * LC, (long long)LC * D_, (long long)LE * D_, 0);
    // 8) r1 += rowsum(relu([att_c|criteria]@Wr+br)); Lrows=LC
    bgemm<true,0,false,true,true><<<dim3(256, 2, 1), blk, GSMEM>>>(
        atcb, crb, Wrb, br, r1_, 2 * D_, D_, D_, D_, LC, 0, 0, 0, LC);
    // 9) r2 += rowsum(relu([att_e|ehr]@Wr+br)); Lrows=LE
    bgemm<true,0,false,true,true><<<dim3(1024, 2, 1), blk, GSMEM>>>(
        ateb, ehb, Wrb, br, r2_, 2 * D_, D_, D_, D_, LE, 0, 0, 0, LE);
    // 10) final MLP -> (B, 3)
    final_mlp<<<B_, 256>>>(r1_, r2_, Wm, bm, Wo, bo, (float*)d_out);
}